// round 4
// baseline (speedup 1.0000x reference)
#include <cuda_runtime.h>
#include <math.h>

#define BB 16
#define NN 4096
#define MM 1024
#define CF 64
#define INCH 67
#define GRPS (BB*MM)          // 16384 centroids total
#define XYZ_OUT ((size_t)BB*MM*3)

// ---------------- device scratch (no allocations allowed) ----------------
__device__ int   g_nbr[(16+32+64)*GRPS];          // neighbor idx, 3 scales packed
__device__ float g_x0[(size_t)64 * GRPS * 64];    // layer-0 activations scratch (256MB)
__device__ float g_rawmax[128 * GRPS];            // raw layer-1 max per (c, centroid)
__device__ float g_rawmin[128 * GRPS];            // raw layer-1 min per (c, centroid)
__device__ float g_stats[512];                    // [0:64)sum0 [128:192)sumsq0 [256:384)sum1 [384:512)sumsq1

__device__ __forceinline__ float sqdist_rn(float dx, float dy, float dz){
    // plain mul/add, no FMA contraction (match XLA elementwise square+sum)
    return __fadd_rn(__fadd_rn(__fmul_rn(dx,dx),__fmul_rn(dy,dy)),__fmul_rn(dz,dz));
}
__device__ __forceinline__ float gelu_exact(float x){
    return 0.5f * x * (1.0f + erff(x * 0.70710678118654752f));
}

// ---------------- 1) farthest point sampling (dist in registers, 2 syncs/iter) ----------------
__global__ void fps_kernel(const float* __restrict__ xyz, float* __restrict__ out_newxyz){
    extern __shared__ float sm[];
    float* sx = sm; float* sy = sm+NN; float* sz = sm+2*NN;
    __shared__ float rv[32]; __shared__ int ri[32];
    int b = blockIdx.x, t = threadIdx.x;
    for (int i=t;i<NN;i+=blockDim.x){
        const float* p = xyz + ((size_t)b*NN+i)*3;
        sx[i]=p[0]; sy[i]=p[1]; sz[i]=p[2];
    }
    __syncthreads();
    float dreg[4] = {1e10f,1e10f,1e10f,1e10f};
    int far = 0;
    for (int it=0; it<MM; it++){
        float cx=sx[far], cy=sy[far], cz=sz[far];
        if (t==0){
            float* o = out_newxyz + ((size_t)b*MM+it)*3;
            o[0]=cx; o[1]=cy; o[2]=cz;
        }
        float best=-1.0f; int bi=0;
        #pragma unroll
        for (int u=0;u<4;u++){
            int i = t + u*1024;
            float d  = sqdist_rn(sx[i]-cx, sy[i]-cy, sz[i]-cz);
            float nd = fminf(dreg[u], d);
            dreg[u]=nd;
            if (nd>best){ best=nd; bi=i; }   // ascending i: strict > keeps smallest index
        }
        #pragma unroll
        for (int o=16;o;o>>=1){
            float ov=__shfl_down_sync(0xffffffffu,best,o);
            int   oi=__shfl_down_sync(0xffffffffu,bi,o);
            if (ov>best || (ov==best && oi<bi)){ best=ov; bi=oi; }
        }
        if ((t&31)==0){ rv[t>>5]=best; ri[t>>5]=bi; }
        __syncthreads();
        if (t<32){
            best=rv[t]; bi=ri[t];
            #pragma unroll
            for (int o=16;o;o>>=1){
                float ov=__shfl_down_sync(0xffffffffu,best,o);
                int   oi=__shfl_down_sync(0xffffffffu,bi,o);
                if (ov>best || (ov==best && oi<bi)){ best=ov; bi=oi; }
            }
            if (t==0) ri[0]=bi;
        }
        __syncthreads();
        far = ri[0];
    }
}

// ---------------- 2) ball query: xyz staged in smem, 8 warps/centroids per block ----------------
__global__ void __launch_bounds__(256)
ballq_kernel(const float* __restrict__ xyz, const float* __restrict__ newxyz){
    extern __shared__ float sm[];
    float* sx = sm; float* sy = sm+NN; float* sz = sm+2*NN;
    int tid = threadIdx.x;
    int gw0 = blockIdx.x*8;               // first centroid of this block
    int b   = gw0 >> 10;                  // batch (8 divides 1024, so single batch/block)
    const float* base = xyz + (size_t)b*NN*3;
    for (int j=tid;j<NN*3;j+=256){
        float v = base[j];
        int idx = j/3, ch = j-idx*3;
        if (ch==0) sx[idx]=v; else if (ch==1) sy[idx]=v; else sz[idx]=v;
    }
    __syncthreads();

    int w    = tid>>5;
    int lane = tid&31;
    int gw   = gw0 + w;
    float cx=newxyz[gw*3+0], cy=newxyz[gw*3+1], cz=newxyz[gw*3+2];
    const float R2_0=(float)(0.1*0.1), R2_1=(float)(0.2*0.2), R2_2=(float)(0.4*0.4);
    int c0=0,c1=0,c2=0, f0=0,f1=0,f2=0;
    int* n0 = g_nbr + gw*16;
    int* n1 = g_nbr + 16*GRPS + gw*32;
    int* n2 = g_nbr + 48*GRPS + gw*64;
    for (int s=0;s<NN;s+=32){
        int i = s + lane;
        float d = sqdist_rn(sx[i]-cx, sy[i]-cy, sz[i]-cz);
        unsigned m0=__ballot_sync(0xffffffffu, d<=R2_0);
        unsigned m1=__ballot_sync(0xffffffffu, d<=R2_1);
        unsigned m2=__ballot_sync(0xffffffffu, d<=R2_2);
        if (m0 && c0<16){
            if (c0==0) f0 = s + __ffs(m0) - 1;
            int r = __popc(m0 & ((1u<<lane)-1u));
            if ((m0>>lane)&1u){ if (c0+r<16) n0[c0+r]=i; }
            c0 += __popc(m0); if (c0>16) c0=16;
        }
        if (m1 && c1<32){
            if (c1==0) f1 = s + __ffs(m1) - 1;
            int r = __popc(m1 & ((1u<<lane)-1u));
            if ((m1>>lane)&1u){ if (c1+r<32) n1[c1+r]=i; }
            c1 += __popc(m1); if (c1>32) c1=32;
        }
        if (m2 && c2<64){
            if (c2==0) f2 = s + __ffs(m2) - 1;
            int r = __popc(m2 & ((1u<<lane)-1u));
            if ((m2>>lane)&1u){ if (c2+r<64) n2[c2+r]=i; }
            c2 += __popc(m2); if (c2>64) c2=64;
        }
        if (c0>=16 && c1>=32 && c2>=64) break;
    }
    for (int j=c0+lane;j<16;j+=32) n0[j]=f0;
    for (int j=c1+lane;j<32;j+=32) n1[j]=f1;
    for (int j=c2+lane;j<64;j+=32) n2[j]=f2;
}

// ---------------- stats zeroing ----------------
__global__ void zero_stats_kernel(){ g_stats[threadIdx.x] = 0.0f; }

// ---------------- 3a) pass A: gather + conv0, accumulate stats0, store X0 ----------------
// Warp-level GEMM mapping: lane = point quad (4 contiguous pts), warp = C0/8 channels.
// bv: ONE conflict-free LDS.128 per kk (32 lanes x 16B contiguous = crossbar floor).
template<int K,int C0>
__global__ void __launch_bounds__(256,2)
passA_kernel(const float* __restrict__ xyz, const float* __restrict__ feat,
             const float* __restrict__ newxyz, int noff,
             const float* __restrict__ w0)
{
    const int P = GRPS*K;
    constexpr int SP = 128;
    extern __shared__ float sm[];
    float* in_s = sm;                  // INCH * SP
    float* w0s  = sm + INCH*SP;        // INCH * C0 (transposed)
    float* st   = w0s + INCH*C0;       // 2*C0
    int tid = threadIdx.x;
    int tp  = blockIdx.x*128;

    for (int i=tid;i<C0*INCH;i+=256){ int c=i/INCH, kk=i-c*INCH; w0s[kk*C0+c]=w0[i]; }
    for (int i=tid;i<2*C0;i+=256) st[i]=0.0f;

    { // gather: 2 threads per point
        int p  = tid>>1, h = tid&1;
        int gp = tp + p;
        int g  = gp / K;
        int idx = g_nbr[noff + gp];
        int b   = g >> 10;
        const float* fs = feat + ((size_t)(b*NN)+idx)*CF;
        if (h==0){
            const float* xs = xyz + ((size_t)(b*NN)+idx)*3;
            in_s[0*SP+p] = xs[0]-newxyz[g*3+0];
            in_s[1*SP+p] = xs[1]-newxyz[g*3+1];
            in_s[2*SP+p] = xs[2]-newxyz[g*3+2];
            #pragma unroll
            for (int q=0;q<8;q++){
                float4 v = *(const float4*)(fs + q*4);
                in_s[(3+q*4+0)*SP+p]=v.x; in_s[(3+q*4+1)*SP+p]=v.y;
                in_s[(3+q*4+2)*SP+p]=v.z; in_s[(3+q*4+3)*SP+p]=v.w;
            }
        } else {
            #pragma unroll
            for (int q=8;q<16;q++){
                float4 v = *(const float4*)(fs + q*4);
                in_s[(3+q*4+0)*SP+p]=v.x; in_s[(3+q*4+1)*SP+p]=v.y;
                in_s[(3+q*4+2)*SP+p]=v.z; in_s[(3+q*4+3)*SP+p]=v.w;
            }
        }
    }
    __syncthreads();

    int ln = tid & 31, w = tid >> 5;        // lane = point quad, warp = channel group
    constexpr int JC = C0/8;                // channels per thread (4 or 8)
    float acc[JC][4];
    #pragma unroll
    for (int j=0;j<JC;j++)
        #pragma unroll
        for (int i=0;i<4;i++) acc[j][i]=0.0f;

    #pragma unroll 4
    for (int kk=0;kk<INCH;kk++){
        float4 b4 = *(const float4*)(in_s + kk*SP + ln*4);   // conflict-free
        float bv[4] = {b4.x, b4.y, b4.z, b4.w};
        float av[JC];
        #pragma unroll
        for (int q=0;q<JC;q+=4){
            float4 a4 = *(const float4*)(w0s + kk*C0 + w*JC + q);  // broadcast
            av[q+0]=a4.x; av[q+1]=a4.y; av[q+2]=a4.z; av[q+3]=a4.w;
        }
        #pragma unroll
        for (int j=0;j<JC;j++)
            #pragma unroll
            for (int i=0;i<4;i++) acc[j][i]=fmaf(av[j],bv[i],acc[j][i]);
    }

    #pragma unroll
    for (int j=0;j<JC;j++){
        int c = w*JC + j;
        float s=0.0f, s2=0.0f;
        #pragma unroll
        for (int i=0;i<4;i++){ float v=acc[j][i]; s+=v; s2+=v*v; }
        *(float4*)(g_x0 + (size_t)c*P + tp + ln*4) =
            make_float4(acc[j][0],acc[j][1],acc[j][2],acc[j][3]);
        atomicAdd(&st[c],     s);
        atomicAdd(&st[C0+c],  s2);
    }
    __syncthreads();
    for (int i=tid;i<C0;i+=256){
        atomicAdd(&g_stats[i],     st[i]);
        atomicAdd(&g_stats[128+i], st[C0+i]);
    }
}

// ---------------- 3b) pass C: norm+gelu(X0) -> conv1 -> min/max over k + stats1 ----------------
template<int K,int C0,int C1>
__global__ void __launch_bounds__(256,2)
passC_kernel(const float* __restrict__ w1,
             const float* __restrict__ g0v, const float* __restrict__ b0v)
{
    const int P = GRPS*K;
    extern __shared__ float sm[];
    float* gs  = sm;                  // C0 * 128 (512B rows)
    float* w1s = gs + C0*128;         // C0 * C1 (transposed)
    float* ab  = w1s + C0*C1;         // 2*C0  (a0, b0)
    float* st  = ab + 2*C0;           // 2*C1
    int tid = threadIdx.x, tp = blockIdx.x*128;

    if (tid < C0){
        float cnt  = (float)P;
        float mean = g_stats[tid]/cnt;
        float var  = g_stats[128+tid]/cnt - mean*mean;
        float a    = g0v[tid]/sqrtf(var + 1e-5f);
        ab[tid]    = a;
        ab[C0+tid] = b0v[tid] - mean*a;
    }
    for (int i=tid;i<C1*C0;i+=256){ int c1=i/C0, kk=i-c1*C0; w1s[kk*C1+c1]=w1[i]; }
    for (int i=tid;i<2*C1;i+=256) st[i]=0.0f;
    __syncthreads();

    for (int i=tid;i<C0*128;i+=256){
        int c=i>>7, p=i&127;
        float v = g_x0[(size_t)c*P + tp + p];
        v = ab[c]*v + ab[C0+c];
        gs[c*128+p] = gelu_exact(v);
    }
    __syncthreads();

    int ln = tid & 31, w = tid >> 5;
    constexpr int JC = C1/8;                // 8 or 16 channels per thread
    float acc[JC][4];
    #pragma unroll
    for (int j=0;j<JC;j++)
        #pragma unroll
        for (int i=0;i<4;i++) acc[j][i]=0.0f;

    #pragma unroll 2
    for (int kk=0;kk<C0;kk++){
        float4 b4 = *(const float4*)(gs + kk*128 + ln*4);    // conflict-free
        float bv[4] = {b4.x, b4.y, b4.z, b4.w};
        float av[JC];
        #pragma unroll
        for (int q=0;q<JC;q+=4){
            float4 a4 = *(const float4*)(w1s + kk*C1 + w*JC + q);  // broadcast
            av[q+0]=a4.x; av[q+1]=a4.y; av[q+2]=a4.z; av[q+3]=a4.w;
        }
        #pragma unroll
        for (int j=0;j<JC;j++)
            #pragma unroll
            for (int i=0;i<4;i++) acc[j][i]=fmaf(av[j],bv[i],acc[j][i]);
    }

    // lane ln holds points tp + ln*4 .. +3 ; group = (ln*4)/K -> LPG = K/4 lanes per group
    constexpr int LPG = K/4;                // 4 / 8 / 16 lanes per group
    int gbase = tp / K;
    #pragma unroll
    for (int j=0;j<JC;j++){
        int c = w*JC + j;
        float s=0.0f, s2=0.0f;
        float mx = -3.4e38f, mn = 3.4e38f;
        #pragma unroll
        for (int i=0;i<4;i++){
            float v=acc[j][i];
            s+=v; s2+=v*v;
            mx=fmaxf(mx,v); mn=fminf(mn,v);
        }
        atomicAdd(&st[c],    s);
        atomicAdd(&st[C1+c], s2);
        #pragma unroll
        for (int o=1;o<LPG;o<<=1){
            mx = fmaxf(mx, __shfl_xor_sync(0xffffffffu,mx,o));
            mn = fminf(mn, __shfl_xor_sync(0xffffffffu,mn,o));
        }
        if ((ln & (LPG-1))==0){
            int g = gbase + ln/LPG;
            g_rawmax[c*GRPS + g] = mx;
            g_rawmin[c*GRPS + g] = mn;
        }
    }
    __syncthreads();
    for (int i=tid;i<C1;i+=256){
        atomicAdd(&g_stats[256+i], st[i]);
        atomicAdd(&g_stats[384+i], st[C1+i]);
    }
}

// ---------------- 3c) finalize: normalize min/max + gelu -> output slice ----------------
// gelu is quasiconvex (valley at x ~ -0.75): max over a set of gelu values is
// attained at the set's min or max; both ends checked after the BN affine.
template<int K,int C1>
__global__ void out_kernel(const float* __restrict__ g1v, const float* __restrict__ b1v,
                           float* __restrict__ out, int chOff)
{
    int i = blockIdx.x*blockDim.x + threadIdx.x;
    if (i >= C1*GRPS) return;
    int c = i / GRPS; int g = i - c*GRPS;
    int b = g >> 10, m = g & 1023;
    float cnt  = (float)(GRPS*K);
    float mean = g_stats[256+c]/cnt;
    float var  = g_stats[384+c]/cnt - mean*mean;
    float a    = g1v[c]/sqrtf(var + 1e-5f);
    float bb   = b1v[c] - mean*a;
    float v1   = a*g_rawmax[c*GRPS + g] + bb;
    float v2   = a*g_rawmin[c*GRPS + g] + bb;
    out[XYZ_OUT + ((size_t)b*320 + chOff + c)*MM + m] = fmaxf(gelu_exact(v1), gelu_exact(v2));
}

// ---------------- launch ----------------
extern "C" void kernel_launch(void* const* d_in, const int* in_sizes, int n_in,
                              void* d_out, int out_size)
{
    // dict order: xyz, features, w00,w01,w10,w11,w20,w21, then interleaved g/b per layer
    const float* xyz  = (const float*)d_in[0];
    const float* feat = (const float*)d_in[1];
    const float* w00  = (const float*)d_in[2];
    const float* w01  = (const float*)d_in[3];
    const float* w10  = (const float*)d_in[4];
    const float* w11  = (const float*)d_in[5];
    const float* w20  = (const float*)d_in[6];
    const float* w21  = (const float*)d_in[7];
    const float* g00  = (const float*)d_in[8];
    const float* b00  = (const float*)d_in[9];
    const float* g01  = (const float*)d_in[10];
    const float* b01  = (const float*)d_in[11];
    const float* g10  = (const float*)d_in[12];
    const float* b10  = (const float*)d_in[13];
    const float* g11  = (const float*)d_in[14];
    const float* b11  = (const float*)d_in[15];
    const float* g20  = (const float*)d_in[16];
    const float* b20  = (const float*)d_in[17];
    const float* g21  = (const float*)d_in[18];
    const float* b21  = (const float*)d_in[19];
    float* out = (float*)d_out;
    float* newxyz = out;   // first B*M*3 floats of output ARE new_xyz

    const int smFPS   = 3*NN*4;
    const int smBQ    = 3*NN*4;
    const int smA32   = (INCH*128 + INCH*32 + 2*32)*4;
    const int smA64   = (INCH*128 + INCH*64 + 2*64)*4;
    const int smC0    = (32*128 + 32*64  + 2*32 + 2*64 )*4;
    const int smC12   = (64*128 + 64*128 + 2*64 + 2*128)*4;

    cudaFuncSetAttribute(fps_kernel,            cudaFuncAttributeMaxDynamicSharedMemorySize, smFPS);
    cudaFuncSetAttribute(ballq_kernel,          cudaFuncAttributeMaxDynamicSharedMemorySize, smBQ);
    cudaFuncSetAttribute(passA_kernel<16,32>,   cudaFuncAttributeMaxDynamicSharedMemorySize, smA32);
    cudaFuncSetAttribute(passA_kernel<32,64>,   cudaFuncAttributeMaxDynamicSharedMemorySize, smA64);
    cudaFuncSetAttribute(passA_kernel<64,64>,   cudaFuncAttributeMaxDynamicSharedMemorySize, smA64);
    cudaFuncSetAttribute(passC_kernel<16,32,64>,  cudaFuncAttributeMaxDynamicSharedMemorySize, smC0);
    cudaFuncSetAttribute(passC_kernel<32,64,128>, cudaFuncAttributeMaxDynamicSharedMemorySize, smC12);
    cudaFuncSetAttribute(passC_kernel<64,64,128>, cudaFuncAttributeMaxDynamicSharedMemorySize, smC12);

    fps_kernel<<<BB, 1024, smFPS>>>(xyz, newxyz);
    ballq_kernel<<<GRPS/8, 256, smBQ>>>(xyz, newxyz);

    // ---- scale 0: k=16, C0=32, C1=64, channel offset 0
    zero_stats_kernel<<<1,512>>>();
    passA_kernel<16,32><<<GRPS*16/128, 256, smA32>>>(xyz, feat, newxyz, 0, w00);
    passC_kernel<16,32,64><<<GRPS*16/128, 256, smC0>>>(w01, g00, b00);
    out_kernel<16,64><<<(64*GRPS)/256, 256>>>(g01, b01, out, 0);

    // ---- scale 1: k=32, C0=64, C1=128, channel offset 64
    zero_stats_kernel<<<1,512>>>();
    passA_kernel<32,64><<<GRPS*32/128, 256, smA64>>>(xyz, feat, newxyz, 16*GRPS, w10);
    passC_kernel<32,64,128><<<GRPS*32/128, 256, smC12>>>(w11, g10, b10);
    out_kernel<32,128><<<(128*GRPS)/256, 256>>>(g11, b11, out, 64);

    // ---- scale 2: k=64, C0=64, C1=128, channel offset 192
    zero_stats_kernel<<<1,512>>>();
    passA_kernel<64,64><<<GRPS*64/128, 256, smA64>>>(xyz, feat, newxyz, 48*GRPS, w20);
    passC_kernel<64,64,128><<<GRPS*64/128, 256, smC12>>>(w21, g20, b20);
    out_kernel<64,128><<<(128*GRPS)/256, 256>>>(g21, b21, out, 192);
}

// round 6
// speedup vs baseline: 1.7283x; 1.7283x over previous
#include <cuda_runtime.h>
#include <math.h>
#include <stdint.h>

#define BB 16
#define NN 4096
#define MM 1024
#define CF 64
#define INCH 67
#define KP 72              // layer-0 K padded to 9 mma k-steps
#define SP 136             // point-row pad (bank-conflict-free fragment loads)
#define GRPS (BB*MM)
#define XYZ_OUT ((size_t)BB*MM*3)

// ---------------- device scratch ----------------
__device__ int   g_nbr[(16+32+64)*GRPS];
__device__ float g_x0[(size_t)64 * GRPS * 64];
__device__ float g_rawmax[128 * GRPS];
__device__ float g_rawmin[128 * GRPS];
__device__ float g_stats[512];

__device__ __forceinline__ float sqdist_rn(float dx, float dy, float dz){
    return __fadd_rn(__fadd_rn(__fmul_rn(dx,dx),__fmul_rn(dy,dy)),__fmul_rn(dz,dz));
}
__device__ __forceinline__ float gelu_exact(float x){
    return 0.5f * x * (1.0f + erff(x * 0.70710678118654752f));
}
// 3xTF32 split: x ~= hi + lo, both tf32-rounded
__device__ __forceinline__ void tf32split(float x, float& hi, float& lo){
    uint32_t h; asm("cvt.rna.tf32.f32 %0, %1;" : "=r"(h) : "f"(x));
    hi = __uint_as_float(h);
    float r = x - hi;
    uint32_t l; asm("cvt.rna.tf32.f32 %0, %1;" : "=r"(l) : "f"(r));
    lo = __uint_as_float(l);
}
__device__ __forceinline__ void mma_tf32(float* d,
    uint32_t a0,uint32_t a1,uint32_t a2,uint32_t a3, uint32_t b0,uint32_t b1){
    asm volatile(
        "mma.sync.aligned.m16n8k8.row.col.f32.tf32.tf32.f32 "
        "{%0,%1,%2,%3}, {%4,%5,%6,%7}, {%8,%9}, {%0,%1,%2,%3};"
        : "+f"(d[0]), "+f"(d[1]), "+f"(d[2]), "+f"(d[3])
        : "r"(a0), "r"(a1), "r"(a2), "r"(a3), "r"(b0), "r"(b1));
}

// ---------------- 1) farthest point sampling ----------------
__global__ void fps_kernel(const float* __restrict__ xyz, float* __restrict__ out_newxyz){
    extern __shared__ float sm[];
    float* sx = sm; float* sy = sm+NN; float* sz = sm+2*NN;
    __shared__ float rv[32]; __shared__ int ri[32];
    int b = blockIdx.x, t = threadIdx.x;
    for (int i=t;i<NN;i+=blockDim.x){
        const float* p = xyz + ((size_t)b*NN+i)*3;
        sx[i]=p[0]; sy[i]=p[1]; sz[i]=p[2];
    }
    __syncthreads();
    float dreg[4] = {1e10f,1e10f,1e10f,1e10f};
    int far = 0;
    for (int it=0; it<MM; it++){
        float cx=sx[far], cy=sy[far], cz=sz[far];
        if (t==0){
            float* o = out_newxyz + ((size_t)b*MM+it)*3;
            o[0]=cx; o[1]=cy; o[2]=cz;
        }
        float best=-1.0f; int bi=0;
        #pragma unroll
        for (int u=0;u<4;u++){
            int i = t + u*1024;
            float d  = sqdist_rn(sx[i]-cx, sy[i]-cy, sz[i]-cz);
            float nd = fminf(dreg[u], d);
            dreg[u]=nd;
            if (nd>best){ best=nd; bi=i; }
        }
        #pragma unroll
        for (int o=16;o;o>>=1){
            float ov=__shfl_down_sync(0xffffffffu,best,o);
            int   oi=__shfl_down_sync(0xffffffffu,bi,o);
            if (ov>best || (ov==best && oi<bi)){ best=ov; bi=oi; }
        }
        if ((t&31)==0){ rv[t>>5]=best; ri[t>>5]=bi; }
        __syncthreads();
        if (t<32){
            best=rv[t]; bi=ri[t];
            #pragma unroll
            for (int o=16;o;o>>=1){
                float ov=__shfl_down_sync(0xffffffffu,best,o);
                int   oi=__shfl_down_sync(0xffffffffu,bi,o);
                if (ov>best || (ov==best && oi<bi)){ best=ov; bi=oi; }
            }
            if (t==0) ri[0]=bi;
        }
        __syncthreads();
        far = ri[0];
    }
}

// ---------------- 2) ball query ----------------
__global__ void __launch_bounds__(256)
ballq_kernel(const float* __restrict__ xyz, const float* __restrict__ newxyz){
    extern __shared__ float sm[];
    float* sx = sm; float* sy = sm+NN; float* sz = sm+2*NN;
    int tid = threadIdx.x;
    int gw0 = blockIdx.x*8;
    int b   = gw0 >> 10;
    const float* base = xyz + (size_t)b*NN*3;
    for (int j=tid;j<NN*3;j+=256){
        float v = base[j];
        int idx = j/3, ch = j-idx*3;
        if (ch==0) sx[idx]=v; else if (ch==1) sy[idx]=v; else sz[idx]=v;
    }
    __syncthreads();
    int w    = tid>>5;
    int lane = tid&31;
    int gw   = gw0 + w;
    float cx=newxyz[gw*3+0], cy=newxyz[gw*3+1], cz=newxyz[gw*3+2];
    const float R2_0=(float)(0.1*0.1), R2_1=(float)(0.2*0.2), R2_2=(float)(0.4*0.4);
    int c0=0,c1=0,c2=0, f0=0,f1=0,f2=0;
    int* n0 = g_nbr + gw*16;
    int* n1 = g_nbr + 16*GRPS + gw*32;
    int* n2 = g_nbr + 48*GRPS + gw*64;
    for (int s=0;s<NN;s+=32){
        int i = s + lane;
        float d = sqdist_rn(sx[i]-cx, sy[i]-cy, sz[i]-cz);
        unsigned m0=__ballot_sync(0xffffffffu, d<=R2_0);
        unsigned m1=__ballot_sync(0xffffffffu, d<=R2_1);
        unsigned m2=__ballot_sync(0xffffffffu, d<=R2_2);
        if (m0 && c0<16){
            if (c0==0) f0 = s + __ffs(m0) - 1;
            int r = __popc(m0 & ((1u<<lane)-1u));
            if ((m0>>lane)&1u){ if (c0+r<16) n0[c0+r]=i; }
            c0 += __popc(m0); if (c0>16) c0=16;
        }
        if (m1 && c1<32){
            if (c1==0) f1 = s + __ffs(m1) - 1;
            int r = __popc(m1 & ((1u<<lane)-1u));
            if ((m1>>lane)&1u){ if (c1+r<32) n1[c1+r]=i; }
            c1 += __popc(m1); if (c1>32) c1=32;
        }
        if (m2 && c2<64){
            if (c2==0) f2 = s + __ffs(m2) - 1;
            int r = __popc(m2 & ((1u<<lane)-1u));
            if ((m2>>lane)&1u){ if (c2+r<64) n2[c2+r]=i; }
            c2 += __popc(m2); if (c2>64) c2=64;
        }
        if (c0>=16 && c1>=32 && c2>=64) break;
    }
    for (int j=c0+lane;j<16;j+=32) n0[j]=f0;
    for (int j=c1+lane;j<32;j+=32) n1[j]=f1;
    for (int j=c2+lane;j<64;j+=32) n2[j]=f2;
}

__global__ void zero_stats_kernel(){ g_stats[threadIdx.x] = 0.0f; }

// ---------------- 3a) pass A: gather + tf32 mma conv0 + stats0 -> g_x0 ----------------
template<int K,int C0>
__global__ void __launch_bounds__(256)
passA_kernel(const float* __restrict__ xyz, const float* __restrict__ feat,
             const float* __restrict__ newxyz, int noff,
             const float* __restrict__ w0)
{
    const int P = GRPS*K;
    extern __shared__ float sm[];
    float* in_hi = sm;                       // KP * SP
    float* in_lo = in_hi + KP*SP;
    float* w_hi  = in_lo + KP*SP;            // C0 * KP
    float* w_lo  = w_hi + C0*KP;
    float* st    = w_lo + C0*KP;             // 2*C0
    int tid = threadIdx.x;
    int tp  = blockIdx.x*128;

    for (int i=tid;i<C0*KP;i+=256){
        int c=i/KP, k=i-c*KP;
        float v = (k<INCH)? w0[c*INCH+k] : 0.0f;
        tf32split(v, w_hi[i], w_lo[i]);
    }
    for (int i=tid;i<2*C0;i+=256) st[i]=0.0f;
    for (int i=tid;i<(KP-INCH)*SP;i+=256){ in_hi[INCH*SP+i]=0.0f; in_lo[INCH*SP+i]=0.0f; }

    { // gather + split: 2 threads per point
        int p  = tid>>1, h = tid&1;
        int gp = tp + p;
        int g  = gp / K;
        int idx = g_nbr[noff + gp];
        int b   = g >> 10;
        const float* fs = feat + ((size_t)(b*NN)+idx)*CF;
        float hi, lo;
        if (h==0){
            const float* xs = xyz + ((size_t)(b*NN)+idx)*3;
            tf32split(xs[0]-newxyz[g*3+0], hi, lo); in_hi[0*SP+p]=hi; in_lo[0*SP+p]=lo;
            tf32split(xs[1]-newxyz[g*3+1], hi, lo); in_hi[1*SP+p]=hi; in_lo[1*SP+p]=lo;
            tf32split(xs[2]-newxyz[g*3+2], hi, lo); in_hi[2*SP+p]=hi; in_lo[2*SP+p]=lo;
            #pragma unroll
            for (int q=0;q<8;q++){
                float4 v = *(const float4*)(fs + q*4);
                tf32split(v.x, hi, lo); in_hi[(3+q*4+0)*SP+p]=hi; in_lo[(3+q*4+0)*SP+p]=lo;
                tf32split(v.y, hi, lo); in_hi[(3+q*4+1)*SP+p]=hi; in_lo[(3+q*4+1)*SP+p]=lo;
                tf32split(v.z, hi, lo); in_hi[(3+q*4+2)*SP+p]=hi; in_lo[(3+q*4+2)*SP+p]=lo;
                tf32split(v.w, hi, lo); in_hi[(3+q*4+3)*SP+p]=hi; in_lo[(3+q*4+3)*SP+p]=lo;
            }
        } else {
            #pragma unroll
            for (int q=8;q<16;q++){
                float4 v = *(const float4*)(fs + q*4);
                tf32split(v.x, hi, lo); in_hi[(3+q*4+0)*SP+p]=hi; in_lo[(3+q*4+0)*SP+p]=lo;
                tf32split(v.y, hi, lo); in_hi[(3+q*4+1)*SP+p]=hi; in_lo[(3+q*4+1)*SP+p]=lo;
                tf32split(v.z, hi, lo); in_hi[(3+q*4+2)*SP+p]=hi; in_lo[(3+q*4+2)*SP+p]=lo;
                tf32split(v.w, hi, lo); in_hi[(3+q*4+3)*SP+p]=hi; in_lo[(3+q*4+3)*SP+p]=lo;
            }
        }
    }
    __syncthreads();

    constexpr int CT = C0/16;      // ch-tiles (2 or 4)
    constexpr int PG = 8/CT;       // point groups
    constexpr int PW = 128/PG;     // points per warp
    constexpr int NT = PW/8;       // n-tiles per warp
    int ln = tid&31, w = tid>>5;
    int g = ln>>2, t = ln&3;
    int ch0 = (w%CT)*16;
    int pb  = (w/CT)*PW;

    float acc[NT][4];
    #pragma unroll
    for (int nt=0;nt<NT;nt++){ acc[nt][0]=0;acc[nt][1]=0;acc[nt][2]=0;acc[nt][3]=0; }

    for (int ks=0; ks<KP/8; ks++){
        int k = ks*8;
        const float* Ah = w_hi + (ch0+g)*KP + k + t;
        const float* Al = w_lo + (ch0+g)*KP + k + t;
        uint32_t a0h=__float_as_uint(Ah[0]),      a1h=__float_as_uint(Ah[8*KP]);
        uint32_t a2h=__float_as_uint(Ah[4]),      a3h=__float_as_uint(Ah[8*KP+4]);
        uint32_t a0l=__float_as_uint(Al[0]),      a1l=__float_as_uint(Al[8*KP]);
        uint32_t a2l=__float_as_uint(Al[4]),      a3l=__float_as_uint(Al[8*KP+4]);
        #pragma unroll
        for (int nt=0;nt<NT;nt++){
            int p = pb + nt*8 + g;
            uint32_t b0h=__float_as_uint(in_hi[(k+t)*SP+p]);
            uint32_t b1h=__float_as_uint(in_hi[(k+t+4)*SP+p]);
            uint32_t b0l=__float_as_uint(in_lo[(k+t)*SP+p]);
            uint32_t b1l=__float_as_uint(in_lo[(k+t+4)*SP+p]);
            mma_tf32(acc[nt], a0h,a1h,a2h,a3h, b0h,b1h);
            mma_tf32(acc[nt], a0h,a1h,a2h,a3h, b0l,b1l);
            mma_tf32(acc[nt], a0l,a1l,a2l,a3l, b0h,b1h);
        }
    }

    // epilogue: store x0 + stats (rows g -> ch0+g, rows g+8 -> ch0+g+8; cols 2t,2t+1)
    float sA=0,sA2=0,sB=0,sB2=0;
    #pragma unroll
    for (int nt=0;nt<NT;nt++){
        float x=acc[nt][0], y=acc[nt][1], z=acc[nt][2], v=acc[nt][3];
        sA += x+y; sA2 += x*x+y*y; sB += z+v; sB2 += z*z+v*v;
        int pofs = tp + pb + nt*8 + 2*t;
        *(float2*)(g_x0 + (size_t)(ch0+g)*P   + pofs) = make_float2(x,y);
        *(float2*)(g_x0 + (size_t)(ch0+g+8)*P + pofs) = make_float2(z,v);
    }
    #pragma unroll
    for (int o=1;o<4;o<<=1){
        sA  += __shfl_xor_sync(0xffffffffu,sA,o);
        sA2 += __shfl_xor_sync(0xffffffffu,sA2,o);
        sB  += __shfl_xor_sync(0xffffffffu,sB,o);
        sB2 += __shfl_xor_sync(0xffffffffu,sB2,o);
    }
    if (t==0){
        atomicAdd(&st[ch0+g],      sA);  atomicAdd(&st[C0+ch0+g],   sA2);
        atomicAdd(&st[ch0+g+8],    sB);  atomicAdd(&st[C0+ch0+g+8], sB2);
    }
    __syncthreads();
    for (int i=tid;i<C0;i+=256){
        atomicAdd(&g_stats[i],     st[i]);
        atomicAdd(&g_stats[128+i], st[C0+i]);
    }
}

// ---------------- 3b) pass C: norm+gelu -> tf32 mma conv1 -> min/max + stats1 ----------------
template<int K,int C0,int C1>
__global__ void __launch_bounds__(256)
passC_kernel(const float* __restrict__ w1,
             const float* __restrict__ g0v, const float* __restrict__ b0v)
{
    const int P = GRPS*K;
    constexpr int C0P = C0 + 8;              // 40 or 72 (bank-safe row stride)
    extern __shared__ float sm[];
    float* gs_hi = sm;                       // C0 * SP
    float* gs_lo = gs_hi + C0*SP;
    float* w_hi  = gs_lo + C0*SP;            // C1 * C0P
    float* w_lo  = w_hi + C1*C0P;
    float* ab    = w_lo + C1*C0P;            // 2*C0
    float* st    = ab + 2*C0;                // 2*C1
    int tid = threadIdx.x, tp = blockIdx.x*128;

    if (tid < C0){
        float cnt  = (float)P;
        float mean = g_stats[tid]/cnt;
        float var  = g_stats[128+tid]/cnt - mean*mean;
        float a    = g0v[tid]/sqrtf(var + 1e-5f);
        ab[tid]    = a;
        ab[C0+tid] = b0v[tid] - mean*a;
    }
    for (int i=tid;i<C1*C0P;i+=256){
        int c=i/C0P, k=i-c*C0P;
        float v = (k<C0)? w1[c*C0+k] : 0.0f;
        tf32split(v, w_hi[i], w_lo[i]);
    }
    for (int i=tid;i<2*C1;i+=256) st[i]=0.0f;
    __syncthreads();

    for (int i=tid;i<C0*128;i+=256){
        int c=i>>7, p=i&127;
        float v = g_x0[(size_t)c*P + tp + p];
        v = gelu_exact(ab[c]*v + ab[C0+c]);
        tf32split(v, gs_hi[c*SP+p], gs_lo[c*SP+p]);
    }
    __syncthreads();

    constexpr int CT = C1/16;      // 4 or 8
    constexpr int PG = 8/CT;       // 2 or 1
    constexpr int PW = 128/PG;     // 64 or 128
    constexpr int NT = PW/8;       // 8 or 16
    int ln = tid&31, w = tid>>5;
    int g = ln>>2, t = ln&3;
    int ch0 = (w%CT)*16;
    int pb  = (w/CT)*PW;

    float acc[NT][4];
    #pragma unroll
    for (int nt=0;nt<NT;nt++){ acc[nt][0]=0;acc[nt][1]=0;acc[nt][2]=0;acc[nt][3]=0; }

    for (int ks=0; ks<C0/8; ks++){
        int k = ks*8;
        const float* Ah = w_hi + (ch0+g)*C0P + k + t;
        const float* Al = w_lo + (ch0+g)*C0P + k + t;
        uint32_t a0h=__float_as_uint(Ah[0]),      a1h=__float_as_uint(Ah[8*C0P]);
        uint32_t a2h=__float_as_uint(Ah[4]),      a3h=__float_as_uint(Ah[8*C0P+4]);
        uint32_t a0l=__float_as_uint(Al[0]),      a1l=__float_as_uint(Al[8*C0P]);
        uint32_t a2l=__float_as_uint(Al[4]),      a3l=__float_as_uint(Al[8*C0P+4]);
        #pragma unroll
        for (int nt=0;nt<NT;nt++){
            int p = pb + nt*8 + g;
            uint32_t b0h=__float_as_uint(gs_hi[(k+t)*SP+p]);
            uint32_t b1h=__float_as_uint(gs_hi[(k+t+4)*SP+p]);
            uint32_t b0l=__float_as_uint(gs_lo[(k+t)*SP+p]);
            uint32_t b1l=__float_as_uint(gs_lo[(k+t+4)*SP+p]);
            mma_tf32(acc[nt], a0h,a1h,a2h,a3h, b0h,b1h);
            mma_tf32(acc[nt], a0h,a1h,a2h,a3h, b0l,b1l);
            mma_tf32(acc[nt], a0l,a1l,a2l,a3l, b0h,b1h);
        }
    }

    // stats
    float sA=0,sA2=0,sB=0,sB2=0;
    #pragma unroll
    for (int nt=0;nt<NT;nt++){
        float x=acc[nt][0], y=acc[nt][1], z=acc[nt][2], v=acc[nt][3];
        sA += x+y; sA2 += x*x+y*y; sB += z+v; sB2 += z*z+v*v;
    }
    #pragma unroll
    for (int o=1;o<4;o<<=1){
        sA  += __shfl_xor_sync(0xffffffffu,sA,o);
        sA2 += __shfl_xor_sync(0xffffffffu,sA2,o);
        sB  += __shfl_xor_sync(0xffffffffu,sB,o);
        sB2 += __shfl_xor_sync(0xffffffffu,sB2,o);
    }
    if (t==0){
        atomicAdd(&st[ch0+g],      sA);  atomicAdd(&st[C1+ch0+g],   sA2);
        atomicAdd(&st[ch0+g+8],    sB);  atomicAdd(&st[C1+ch0+g+8], sB2);
    }

    // min/max per k-group (group = K consecutive points = K/8 n-tiles)
    constexpr int NTPG = K/8;
    constexpr int NG   = NT/NTPG;
    int gbase = (tp + pb)/K;
    #pragma unroll
    for (int gi=0; gi<NG; gi++){
        float mxA=-3.4e38f, mnA=3.4e38f, mxB=-3.4e38f, mnB=3.4e38f;
        #pragma unroll
        for (int u=0; u<NTPG; u++){
            float* a = acc[gi*NTPG+u];
            mxA=fmaxf(mxA,fmaxf(a[0],a[1])); mnA=fminf(mnA,fminf(a[0],a[1]));
            mxB=fmaxf(mxB,fmaxf(a[2],a[3])); mnB=fminf(mnB,fminf(a[2],a[3]));
        }
        #pragma unroll
        for (int o=1;o<4;o<<=1){
            mxA=fmaxf(mxA,__shfl_xor_sync(0xffffffffu,mxA,o));
            mnA=fminf(mnA,__shfl_xor_sync(0xffffffffu,mnA,o));
            mxB=fmaxf(mxB,__shfl_xor_sync(0xffffffffu,mxB,o));
            mnB=fminf(mnB,__shfl_xor_sync(0xffffffffu,mnB,o));
        }
        if (t==0){
            int gg = gbase + gi;
            g_rawmax[(ch0+g)*GRPS   + gg] = mxA;  g_rawmin[(ch0+g)*GRPS   + gg] = mnA;
            g_rawmax[(ch0+g+8)*GRPS + gg] = mxB;  g_rawmin[(ch0+g+8)*GRPS + gg] = mnB;
        }
    }
    __syncthreads();
    for (int i=tid;i<C1;i+=256){
        atomicAdd(&g_stats[256+i], st[i]);
        atomicAdd(&g_stats[384+i], st[C1+i]);
    }
}

// ---------------- 3c) finalize ----------------
// gelu is quasiconvex: max over the k-set of gelu values is attained at the
// set's raw min or max, both checked after the BN affine.
template<int K,int C1>
__global__ void out_kernel(const float* __restrict__ g1v, const float* __restrict__ b1v,
                           float* __restrict__ out, int chOff)
{
    int i = blockIdx.x*blockDim.x + threadIdx.x;
    if (i >= C1*GRPS) return;
    int c = i / GRPS; int g = i - c*GRPS;
    int b = g >> 10, m = g & 1023;
    float cnt  = (float)(GRPS*K);
    float mean = g_stats[256+c]/cnt;
    float var  = g_stats[384+c]/cnt - mean*mean;
    float a    = g1v[c]/sqrtf(var + 1e-5f);
    float bb   = b1v[c] - mean*a;
    float v1   = a*g_rawmax[c*GRPS + g] + bb;
    float v2   = a*g_rawmin[c*GRPS + g] + bb;
    out[XYZ_OUT + ((size_t)b*320 + chOff + c)*MM + m] = fmaxf(gelu_exact(v1), gelu_exact(v2));
}

// ---------------- launch ----------------
extern "C" void kernel_launch(void* const* d_in, const int* in_sizes, int n_in,
                              void* d_out, int out_size)
{
    const float* xyz  = (const float*)d_in[0];
    const float* feat = (const float*)d_in[1];
    const float* w00  = (const float*)d_in[2];
    const float* w01  = (const float*)d_in[3];
    const float* w10  = (const float*)d_in[4];
    const float* w11  = (const float*)d_in[5];
    const float* w20  = (const float*)d_in[6];
    const float* w21  = (const float*)d_in[7];
    const float* g00  = (const float*)d_in[8];
    const float* b00  = (const float*)d_in[9];
    const float* g01  = (const float*)d_in[10];
    const float* b01  = (const float*)d_in[11];
    const float* g10  = (const float*)d_in[12];
    const float* b10  = (const float*)d_in[13];
    const float* g11  = (const float*)d_in[14];
    const float* b11  = (const float*)d_in[15];
    const float* g20  = (const float*)d_in[16];
    const float* b20  = (const float*)d_in[17];
    const float* g21  = (const float*)d_in[18];
    const float* b21  = (const float*)d_in[19];
    float* out = (float*)d_out;
    float* newxyz = out;

    const int smFPS = 3*NN*4;
    const int smBQ  = 3*NN*4;
    const int smA32 = (2*KP*SP + 2*32*KP + 2*32)*4;
    const int smA64 = (2*KP*SP + 2*64*KP + 2*64)*4;
    const int smC0  = (2*32*SP + 2*64*40  + 2*32 + 2*64 )*4;
    const int smC12 = (2*64*SP + 2*128*72 + 2*64 + 2*128)*4;

    cudaFuncSetAttribute(fps_kernel,            cudaFuncAttributeMaxDynamicSharedMemorySize, smFPS);
    cudaFuncSetAttribute(ballq_kernel,          cudaFuncAttributeMaxDynamicSharedMemorySize, smBQ);
    cudaFuncSetAttribute(passA_kernel<16,32>,   cudaFuncAttributeMaxDynamicSharedMemorySize, smA32);
    cudaFuncSetAttribute(passA_kernel<32,64>,   cudaFuncAttributeMaxDynamicSharedMemorySize, smA64);
    cudaFuncSetAttribute(passA_kernel<64,64>,   cudaFuncAttributeMaxDynamicSharedMemorySize, smA64);
    cudaFuncSetAttribute(passC_kernel<16,32,64>,  cudaFuncAttributeMaxDynamicSharedMemorySize, smC0);
    cudaFuncSetAttribute(passC_kernel<32,64,128>, cudaFuncAttributeMaxDynamicSharedMemorySize, smC12);
    cudaFuncSetAttribute(passC_kernel<64,64,128>, cudaFuncAttributeMaxDynamicSharedMemorySize, smC12);

    fps_kernel<<<BB, 1024, smFPS>>>(xyz, newxyz);
    ballq_kernel<<<GRPS/8, 256, smBQ>>>(xyz, newxyz);

    // scale 0
    zero_stats_kernel<<<1,512>>>();
    passA_kernel<16,32><<<GRPS*16/128, 256, smA32>>>(xyz, feat, newxyz, 0, w00);
    passC_kernel<16,32,64><<<GRPS*16/128, 256, smC0>>>(w01, g00, b00);
    out_kernel<16,64><<<(64*GRPS)/256, 256>>>(g01, b01, out, 0);

    // scale 1
    zero_stats_kernel<<<1,512>>>();
    passA_kernel<32,64><<<GRPS*32/128, 256, smA64>>>(xyz, feat, newxyz, 16*GRPS, w10);
    passC_kernel<32,64,128><<<GRPS*32/128, 256, smC12>>>(w11, g10, b10);
    out_kernel<32,128><<<(128*GRPS)/256, 256>>>(g11, b11, out, 64);

    // scale 2
    zero_stats_kernel<<<1,512>>>();
    passA_kernel<64,64><<<GRPS*64/128, 256, smA64>>>(xyz, feat, newxyz, 48*GRPS, w20);
    passC_kernel<64,64,128><<<GRPS*64/128, 256, smC12>>>(w21, g20, b20);
    out_kernel<64,128><<<(128*GRPS)/256, 256>>>(g21, b21, out, 192);
}

// round 7
// speedup vs baseline: 2.1899x; 1.2671x over previous
#include <cuda_runtime.h>
#include <math.h>
#include <stdint.h>

#define BB 16
#define NN 4096
#define MM 1024
#define CF 64
#define INCH 67
#define GRPS (BB*MM)
#define XYZ_OUT ((size_t)BB*MM*3)

// ---------------- device scratch ----------------
__device__ int   g_nbr[(16+32+64)*GRPS];
__device__ float g_x0[(size_t)64 * GRPS * 64];
__device__ float g_rawmax[128 * GRPS];
__device__ float g_rawmin[128 * GRPS];
__device__ float g_stats[512];

__device__ __forceinline__ float sqdist_rn(float dx, float dy, float dz){
    return __fadd_rn(__fadd_rn(__fmul_rn(dx,dx),__fmul_rn(dy,dy)),__fmul_rn(dz,dz));
}
__device__ __forceinline__ float gelu_exact(float x){
    return 0.5f * x * (1.0f + erff(x * 0.70710678118654752f));
}
__device__ __forceinline__ void tf32split(float x, float& hi, float& lo){
    uint32_t h; asm("cvt.rna.tf32.f32 %0, %1;" : "=r"(h) : "f"(x));
    hi = __uint_as_float(h);
    float r = x - hi;
    uint32_t l; asm("cvt.rna.tf32.f32 %0, %1;" : "=r"(l) : "f"(r));
    lo = __uint_as_float(l);
}
__device__ __forceinline__ void mma_tf32(float* d,
    uint32_t a0,uint32_t a1,uint32_t a2,uint32_t a3, uint32_t b0,uint32_t b1){
    asm volatile(
        "mma.sync.aligned.m16n8k8.row.col.f32.tf32.tf32.f32 "
        "{%0,%1,%2,%3}, {%4,%5,%6,%7}, {%8,%9}, {%0,%1,%2,%3};"
        : "+f"(d[0]), "+f"(d[1]), "+f"(d[2]), "+f"(d[3])
        : "r"(a0), "r"(a1), "r"(a2), "r"(a3), "r"(b0), "r"(b1));
}
// issue the 3xTF32 triple for one 16x8x8 tile
__device__ __forceinline__ void mma3(float* acc, const float4& ah, const float4& al, const float4& bb){
    mma_tf32(acc, __float_as_uint(ah.x),__float_as_uint(ah.y),__float_as_uint(ah.z),__float_as_uint(ah.w),
                  __float_as_uint(bb.x),__float_as_uint(bb.y));
    mma_tf32(acc, __float_as_uint(ah.x),__float_as_uint(ah.y),__float_as_uint(ah.z),__float_as_uint(ah.w),
                  __float_as_uint(bb.z),__float_as_uint(bb.w));
    mma_tf32(acc, __float_as_uint(al.x),__float_as_uint(al.y),__float_as_uint(al.z),__float_as_uint(al.w),
                  __float_as_uint(bb.x),__float_as_uint(bb.y));
}

// ---------------- 1) farthest point sampling ----------------
__global__ void fps_kernel(const float* __restrict__ xyz, float* __restrict__ out_newxyz){
    extern __shared__ float sm[];
    float* sx = sm; float* sy = sm+NN; float* sz = sm+2*NN;
    __shared__ float rv[32]; __shared__ int ri[32];
    int b = blockIdx.x, t = threadIdx.x;
    for (int i=t;i<NN;i+=blockDim.x){
        const float* p = xyz + ((size_t)b*NN+i)*3;
        sx[i]=p[0]; sy[i]=p[1]; sz[i]=p[2];
    }
    __syncthreads();
    float dreg[4] = {1e10f,1e10f,1e10f,1e10f};
    int far = 0;
    for (int it=0; it<MM; it++){
        float cx=sx[far], cy=sy[far], cz=sz[far];
        if (t==0){
            float* o = out_newxyz + ((size_t)b*MM+it)*3;
            o[0]=cx; o[1]=cy; o[2]=cz;
        }
        float best=-1.0f; int bi=0;
        #pragma unroll
        for (int u=0;u<4;u++){
            int i = t + u*1024;
            float d  = sqdist_rn(sx[i]-cx, sy[i]-cy, sz[i]-cz);
            float nd = fminf(dreg[u], d);
            dreg[u]=nd;
            if (nd>best){ best=nd; bi=i; }
        }
        #pragma unroll
        for (int o=16;o;o>>=1){
            float ov=__shfl_down_sync(0xffffffffu,best,o);
            int   oi=__shfl_down_sync(0xffffffffu,bi,o);
            if (ov>best || (ov==best && oi<bi)){ best=ov; bi=oi; }
        }
        if ((t&31)==0){ rv[t>>5]=best; ri[t>>5]=bi; }
        __syncthreads();
        if (t<32){
            best=rv[t]; bi=ri[t];
            #pragma unroll
            for (int o=16;o;o>>=1){
                float ov=__shfl_down_sync(0xffffffffu,best,o);
                int   oi=__shfl_down_sync(0xffffffffu,bi,o);
                if (ov>best || (ov==best && oi<bi)){ best=ov; bi=oi; }
            }
            if (t==0) ri[0]=bi;
        }
        __syncthreads();
        far = ri[0];
    }
}

// ---------------- 2) ball query ----------------
__global__ void __launch_bounds__(256)
ballq_kernel(const float* __restrict__ xyz, const float* __restrict__ newxyz){
    extern __shared__ float sm[];
    float* sx = sm; float* sy = sm+NN; float* sz = sm+2*NN;
    int tid = threadIdx.x;
    int gw0 = blockIdx.x*8;
    int b   = gw0 >> 10;
    const float* base = xyz + (size_t)b*NN*3;
    for (int j=tid;j<NN*3;j+=256){
        float v = base[j];
        int idx = j/3, ch = j-idx*3;
        if (ch==0) sx[idx]=v; else if (ch==1) sy[idx]=v; else sz[idx]=v;
    }
    __syncthreads();
    int w    = tid>>5;
    int lane = tid&31;
    int gw   = gw0 + w;
    float cx=newxyz[gw*3+0], cy=newxyz[gw*3+1], cz=newxyz[gw*3+2];
    const float R2_0=(float)(0.1*0.1), R2_1=(float)(0.2*0.2), R2_2=(float)(0.4*0.4);
    int c0=0,c1=0,c2=0, f0=0,f1=0,f2=0;
    int* n0 = g_nbr + gw*16;
    int* n1 = g_nbr + 16*GRPS + gw*32;
    int* n2 = g_nbr + 48*GRPS + gw*64;
    for (int s=0;s<NN;s+=32){
        int i = s + lane;
        float d = sqdist_rn(sx[i]-cx, sy[i]-cy, sz[i]-cz);
        unsigned m0=__ballot_sync(0xffffffffu, d<=R2_0);
        unsigned m1=__ballot_sync(0xffffffffu, d<=R2_1);
        unsigned m2=__ballot_sync(0xffffffffu, d<=R2_2);
        if (m0 && c0<16){
            if (c0==0) f0 = s + __ffs(m0) - 1;
            int r = __popc(m0 & ((1u<<lane)-1u));
            if ((m0>>lane)&1u){ if (c0+r<16) n0[c0+r]=i; }
            c0 += __popc(m0); if (c0>16) c0=16;
        }
        if (m1 && c1<32){
            if (c1==0) f1 = s + __ffs(m1) - 1;
            int r = __popc(m1 & ((1u<<lane)-1u));
            if ((m1>>lane)&1u){ if (c1+r<32) n1[c1+r]=i; }
            c1 += __popc(m1); if (c1>32) c1=32;
        }
        if (m2 && c2<64){
            if (c2==0) f2 = s + __ffs(m2) - 1;
            int r = __popc(m2 & ((1u<<lane)-1u));
            if ((m2>>lane)&1u){ if (c2+r<64) n2[c2+r]=i; }
            c2 += __popc(m2); if (c2>64) c2=64;
        }
        if (c0>=16 && c1>=32 && c2>=64) break;
    }
    for (int j=c0+lane;j<16;j+=32) n0[j]=f0;
    for (int j=c1+lane;j<32;j+=32) n1[j]=f1;
    for (int j=c2+lane;j<64;j+=32) n2[j]=f2;
}

__global__ void zero_stats_kernel(){ g_stats[threadIdx.x] = 0.0f; }

// ---------------- 3a) pass A: gather + fragment-packed tf32 mma conv0 ----------------
template<int K,int C0>
__global__ void __launch_bounds__(256)
passA_kernel(const float* __restrict__ xyz, const float* __restrict__ feat,
             const float* __restrict__ newxyz, int noff,
             const float* __restrict__ w0)
{
    const int P = GRPS*K;
    constexpr int KS = 9;                 // 72/8 k-steps
    constexpr int CT = C0/16;
    extern __shared__ float smf[];
    float4* inb4 = (float4*)smf;                 // KS*128*4 fragment-packed input
    float4* wh4  = inb4 + KS*128*4;              // KS*CT*32
    float4* wl4  = wh4 + KS*CT*32;
    float*  st   = (float*)(wl4 + KS*CT*32);     // 2*C0
    float*  inbf = smf;
    int tid = threadIdx.x;
    int tp  = blockIdx.x*128;

    // weight fragments (hi/lo), zero-padded beyond INCH
    for (int i=tid;i<KS*CT*32;i+=256){
        int ks=i/(CT*32), rem=i-ks*CT*32, ct=rem>>5, ln=rem&31;
        int g=ln>>2, t=ln&3, c0=ct*16, k=ks*8;
        float4 H,L; float v;
        v = (k+t  <INCH)? w0[(c0+g  )*INCH + k+t  ] : 0.0f; tf32split(v,H.x,L.x);
        v = (k+t  <INCH)? w0[(c0+g+8)*INCH + k+t  ] : 0.0f; tf32split(v,H.y,L.y);
        v = (k+t+4<INCH)? w0[(c0+g  )*INCH + k+t+4] : 0.0f; tf32split(v,H.z,L.z);
        v = (k+t+4<INCH)? w0[(c0+g+8)*INCH + k+t+4] : 0.0f; tf32split(v,H.w,L.w);
        wh4[i]=H; wl4[i]=L;
    }
    for (int i=tid;i<2*C0;i+=256) st[i]=0.0f;
    for (int i=tid;i<512;i+=256) inb4[8*128*4 + i] = make_float4(0,0,0,0);  // pad k-step 8
    __syncthreads();

    { // gather into fragment-packed layout (2 threads per point)
        int p  = tid>>1, h = tid&1;
        int gp = tp + p;
        int g  = gp / K;
        int idx = g_nbr[noff + gp];
        int b   = g >> 10;
        const float* fs = feat + ((size_t)(b*NN)+idx)*CF;
        auto put = [&](int k, float val){
            float hi,lo; tf32split(val,hi,lo);
            int ks=k>>3, r=k&7, t=r&3, half=r>>2;
            int o = ((((ks<<7)+p)<<2)+t)*4 + half;
            inbf[o] = hi; inbf[o+2] = lo;
        };
        if (h==0){
            const float* xs = xyz + ((size_t)(b*NN)+idx)*3;
            put(0, xs[0]-newxyz[g*3+0]);
            put(1, xs[1]-newxyz[g*3+1]);
            put(2, xs[2]-newxyz[g*3+2]);
            #pragma unroll
            for (int q=0;q<8;q++){
                float4 v = *(const float4*)(fs + q*4);
                put(3+q*4+0, v.x); put(3+q*4+1, v.y);
                put(3+q*4+2, v.z); put(3+q*4+3, v.w);
            }
        } else {
            #pragma unroll
            for (int q=8;q<16;q++){
                float4 v = *(const float4*)(fs + q*4);
                put(3+q*4+0, v.x); put(3+q*4+1, v.y);
                put(3+q*4+2, v.z); put(3+q*4+3, v.w);
            }
        }
    }
    __syncthreads();

    constexpr int PG = 8/CT;
    constexpr int PW = 128/PG;
    constexpr int NT = PW/8;
    int ln = tid&31, w = tid>>5;
    int g = ln>>2, t = ln&3;
    int ct = w%CT;
    int ch0 = ct*16;
    int pb  = (w/CT)*PW;

    float acc[NT][4];
    #pragma unroll
    for (int nt=0;nt<NT;nt++){ acc[nt][0]=0;acc[nt][1]=0;acc[nt][2]=0;acc[nt][3]=0; }

    for (int ks=0; ks<KS; ks++){
        float4 ah = wh4[(ks*CT+ct)*32+ln];
        float4 al = wl4[(ks*CT+ct)*32+ln];
        #pragma unroll
        for (int nt=0;nt<NT;nt++){
            float4 bb = inb4[((ks<<7) + pb + nt*8 + g)*4 + t];
            mma3(acc[nt], ah, al, bb);
        }
    }

    float sA=0,sA2=0,sB=0,sB2=0;
    #pragma unroll
    for (int nt=0;nt<NT;nt++){
        float x=acc[nt][0], y=acc[nt][1], z=acc[nt][2], v=acc[nt][3];
        sA += x+y; sA2 += x*x+y*y; sB += z+v; sB2 += z*z+v*v;
        int pofs = tp + pb + nt*8 + 2*t;
        *(float2*)(g_x0 + (size_t)(ch0+g)*P   + pofs) = make_float2(x,y);
        *(float2*)(g_x0 + (size_t)(ch0+g+8)*P + pofs) = make_float2(z,v);
    }
    #pragma unroll
    for (int o=1;o<4;o<<=1){
        sA  += __shfl_xor_sync(0xffffffffu,sA,o);
        sA2 += __shfl_xor_sync(0xffffffffu,sA2,o);
        sB  += __shfl_xor_sync(0xffffffffu,sB,o);
        sB2 += __shfl_xor_sync(0xffffffffu,sB2,o);
    }
    if (t==0){
        atomicAdd(&st[ch0+g],      sA);  atomicAdd(&st[C0+ch0+g],   sA2);
        atomicAdd(&st[ch0+g+8],    sB);  atomicAdd(&st[C0+ch0+g+8], sB2);
    }
    __syncthreads();
    for (int i=tid;i<C0;i+=256){
        atomicAdd(&g_stats[i],     st[i]);
        atomicAdd(&g_stats[128+i], st[C0+i]);
    }
}

// ---------------- 3b) pass C: norm+gelu -> fragment-packed tf32 mma conv1 ----------------
template<int K,int C0,int C1,int PTS,int NTH>
__global__ void __launch_bounds__(NTH)
passC_kernel(const float* __restrict__ w1,
             const float* __restrict__ g0v, const float* __restrict__ b0v)
{
    const int P = GRPS*K;
    constexpr int KS = C0/8;
    constexpr int CT = C1/16;
    extern __shared__ float smf[];
    float4* gsb4 = (float4*)smf;                 // KS*PTS*4
    float4* wh4  = gsb4 + KS*PTS*4;              // KS*CT*32
    float4* wl4  = wh4 + KS*CT*32;
    float*  ab   = (float*)(wl4 + KS*CT*32);     // 2*C0
    float*  st   = ab + 2*C0;                    // 2*C1
    float*  gsf  = smf;
    int tid = threadIdx.x, tp = blockIdx.x*PTS;

    if (tid < C0){
        float cnt  = (float)P;
        float mean = g_stats[tid]/cnt;
        float var  = g_stats[128+tid]/cnt - mean*mean;
        float a    = g0v[tid]/sqrtf(var + 1e-5f);
        ab[tid]    = a;
        ab[C0+tid] = b0v[tid] - mean*a;
    }
    for (int i=tid;i<KS*CT*32;i+=NTH){
        int ks=i/(CT*32), rem=i-ks*CT*32, ct=rem>>5, ln=rem&31;
        int g=ln>>2, t=ln&3, c0=ct*16, k=ks*8;
        float4 H,L;
        tf32split(w1[(c0+g  )*C0 + k+t  ], H.x, L.x);
        tf32split(w1[(c0+g+8)*C0 + k+t  ], H.y, L.y);
        tf32split(w1[(c0+g  )*C0 + k+t+4], H.z, L.z);
        tf32split(w1[(c0+g+8)*C0 + k+t+4], H.w, L.w);
        wh4[i]=H; wl4[i]=L;
    }
    for (int i=tid;i<2*C1;i+=NTH) st[i]=0.0f;
    __syncthreads();

    for (int i=tid;i<C0*PTS;i+=NTH){
        int c=i/PTS, p=i-c*PTS;
        float v = g_x0[(size_t)c*P + tp + p];
        v = gelu_exact(ab[c]*v + ab[C0+c]);
        float hi,lo; tf32split(v,hi,lo);
        int ks=c>>3, r=c&7, t=r&3, half=r>>2;
        int o = ((ks*PTS+p)*4+t)*4 + half;
        gsf[o] = hi; gsf[o+2] = lo;
    }
    __syncthreads();

    constexpr int NW = NTH/32;
    constexpr int PG = NW/CT;
    constexpr int PW = PTS/PG;
    constexpr int NT = PW/8;
    int ln = tid&31, w = tid>>5;
    int g = ln>>2, t = ln&3;
    int ct = w%CT;
    int ch0 = ct*16;
    int pb  = (w/CT)*PW;

    float acc[NT][4];
    #pragma unroll
    for (int nt=0;nt<NT;nt++){ acc[nt][0]=0;acc[nt][1]=0;acc[nt][2]=0;acc[nt][3]=0; }

    for (int ks=0; ks<KS; ks++){
        float4 ah = wh4[(ks*CT+ct)*32+ln];
        float4 al = wl4[(ks*CT+ct)*32+ln];
        #pragma unroll
        for (int nt=0;nt<NT;nt++){
            float4 bb = gsb4[(ks*PTS + pb + nt*8 + g)*4 + t];
            mma3(acc[nt], ah, al, bb);
        }
    }

    float sA=0,sA2=0,sB=0,sB2=0;
    #pragma unroll
    for (int nt=0;nt<NT;nt++){
        float x=acc[nt][0], y=acc[nt][1], z=acc[nt][2], v=acc[nt][3];
        sA += x+y; sA2 += x*x+y*y; sB += z+v; sB2 += z*z+v*v;
    }
    #pragma unroll
    for (int o=1;o<4;o<<=1){
        sA  += __shfl_xor_sync(0xffffffffu,sA,o);
        sA2 += __shfl_xor_sync(0xffffffffu,sA2,o);
        sB  += __shfl_xor_sync(0xffffffffu,sB,o);
        sB2 += __shfl_xor_sync(0xffffffffu,sB2,o);
    }
    if (t==0){
        atomicAdd(&st[ch0+g],      sA);  atomicAdd(&st[C1+ch0+g],   sA2);
        atomicAdd(&st[ch0+g+8],    sB);  atomicAdd(&st[C1+ch0+g+8], sB2);
    }

    constexpr int NTPG = K/8;
    constexpr int NG   = NT/NTPG;
    int gbase = (tp + pb)/K;
    #pragma unroll
    for (int gi=0; gi<NG; gi++){
        float mxA=-3.4e38f, mnA=3.4e38f, mxB=-3.4e38f, mnB=3.4e38f;
        #pragma unroll
        for (int u=0; u<NTPG; u++){
            float* a = acc[gi*NTPG+u];
            mxA=fmaxf(mxA,fmaxf(a[0],a[1])); mnA=fminf(mnA,fminf(a[0],a[1]));
            mxB=fmaxf(mxB,fmaxf(a[2],a[3])); mnB=fminf(mnB,fminf(a[2],a[3]));
        }
        #pragma unroll
        for (int o=1;o<4;o<<=1){
            mxA=fmaxf(mxA,__shfl_xor_sync(0xffffffffu,mxA,o));
            mnA=fminf(mnA,__shfl_xor_sync(0xffffffffu,mnA,o));
            mxB=fmaxf(mxB,__shfl_xor_sync(0xffffffffu,mxB,o));
            mnB=fminf(mnB,__shfl_xor_sync(0xffffffffu,mnB,o));
        }
        if (t==0){
            int gg = gbase + gi;
            g_rawmax[(ch0+g)*GRPS   + gg] = mxA;  g_rawmin[(ch0+g)*GRPS   + gg] = mnA;
            g_rawmax[(ch0+g+8)*GRPS + gg] = mxB;  g_rawmin[(ch0+g+8)*GRPS + gg] = mnB;
        }
    }
    __syncthreads();
    for (int i=tid;i<C1;i+=NTH){
        atomicAdd(&g_stats[256+i], st[i]);
        atomicAdd(&g_stats[384+i], st[C1+i]);
    }
}

// ---------------- 3c) finalize ----------------
template<int K,int C1>
__global__ void out_kernel(const float* __restrict__ g1v, const float* __restrict__ b1v,
                           float* __restrict__ out, int chOff)
{
    int i = blockIdx.x*blockDim.x + threadIdx.x;
    if (i >= C1*GRPS) return;
    int c = i / GRPS; int g = i - c*GRPS;
    int b = g >> 10, m = g & 1023;
    float cnt  = (float)(GRPS*K);
    float mean = g_stats[256+c]/cnt;
    float var  = g_stats[384+c]/cnt - mean*mean;
    float a    = g1v[c]/sqrtf(var + 1e-5f);
    float bb   = b1v[c] - mean*a;
    float v1   = a*g_rawmax[c*GRPS + g] + bb;
    float v2   = a*g_rawmin[c*GRPS + g] + bb;
    out[XYZ_OUT + ((size_t)b*320 + chOff + c)*MM + m] = fmaxf(gelu_exact(v1), gelu_exact(v2));
}

// ---------------- launch ----------------
extern "C" void kernel_launch(void* const* d_in, const int* in_sizes, int n_in,
                              void* d_out, int out_size)
{
    const float* xyz  = (const float*)d_in[0];
    const float* feat = (const float*)d_in[1];
    const float* w00  = (const float*)d_in[2];
    const float* w01  = (const float*)d_in[3];
    const float* w10  = (const float*)d_in[4];
    const float* w11  = (const float*)d_in[5];
    const float* w20  = (const float*)d_in[6];
    const float* w21  = (const float*)d_in[7];
    const float* g00  = (const float*)d_in[8];
    const float* b00  = (const float*)d_in[9];
    const float* g01  = (const float*)d_in[10];
    const float* b01  = (const float*)d_in[11];
    const float* g10  = (const float*)d_in[12];
    const float* b10  = (const float*)d_in[13];
    const float* g11  = (const float*)d_in[14];
    const float* b11  = (const float*)d_in[15];
    const float* g20  = (const float*)d_in[16];
    const float* b20  = (const float*)d_in[17];
    const float* g21  = (const float*)d_in[18];
    const float* b21  = (const float*)d_in[19];
    float* out = (float*)d_out;
    float* newxyz = out;

    const int smFPS = 3*NN*4;
    const int smBQ  = 3*NN*4;
    const int smA32 = (9*128*4 + 2*9*2*32)*16 + 2*32*4;
    const int smA64 = (9*128*4 + 2*9*4*32)*16 + 2*64*4;
    const int smC0  = (4*128*4 + 2*4*4*32)*16 + (2*32 + 2*64)*4;
    const int smC12 = (8*256*4 + 2*8*8*32)*16 + (2*64 + 2*128)*4;

    cudaFuncSetAttribute(fps_kernel,          cudaFuncAttributeMaxDynamicSharedMemorySize, smFPS);
    cudaFuncSetAttribute(ballq_kernel,        cudaFuncAttributeMaxDynamicSharedMemorySize, smBQ);
    cudaFuncSetAttribute(passA_kernel<16,32>, cudaFuncAttributeMaxDynamicSharedMemorySize, smA32);
    cudaFuncSetAttribute(passA_kernel<32,64>, cudaFuncAttributeMaxDynamicSharedMemorySize, smA64);
    cudaFuncSetAttribute(passA_kernel<64,64>, cudaFuncAttributeMaxDynamicSharedMemorySize, smA64);
    cudaFuncSetAttribute(passC_kernel<16,32,64,128,256>,  cudaFuncAttributeMaxDynamicSharedMemorySize, smC0);
    cudaFuncSetAttribute(passC_kernel<32,64,128,256,512>, cudaFuncAttributeMaxDynamicSharedMemorySize, smC12);
    cudaFuncSetAttribute(passC_kernel<64,64,128,256,512>, cudaFuncAttributeMaxDynamicSharedMemorySize, smC12);

    fps_kernel<<<BB, 1024, smFPS>>>(xyz, newxyz);
    ballq_kernel<<<GRPS/8, 256, smBQ>>>(xyz, newxyz);

    // scale 0: k=16, C0=32, C1=64
    zero_stats_kernel<<<1,512>>>();
    passA_kernel<16,32><<<GRPS*16/128, 256, smA32>>>(xyz, feat, newxyz, 0, w00);
    passC_kernel<16,32,64,128,256><<<GRPS*16/128, 256, smC0>>>(w01, g00, b00);
    out_kernel<16,64><<<(64*GRPS)/256, 256>>>(g01, b01, out, 0);

    // scale 1: k=32, C0=64, C1=128
    zero_stats_kernel<<<1,512>>>();
    passA_kernel<32,64><<<GRPS*32/128, 256, smA64>>>(xyz, feat, newxyz, 16*GRPS, w10);
    passC_kernel<32,64,128,256,512><<<GRPS*32/256, 512, smC12>>>(w11, g10, b10);
    out_kernel<32,128><<<(128*GRPS)/256, 256>>>(g11, b11, out, 64);

    // scale 2: k=64, C0=64, C1=128
    zero_stats_kernel<<<1,512>>>();
    passA_kernel<64,64><<<GRPS*64/128, 256, smA64>>>(xyz, feat, newxyz, 48*GRPS, w20);
    passC_kernel<64,64,128,256,512><<<GRPS*64/256, 512, smC12>>>(w21, g20, b20);
    out_kernel<64,128><<<(128*GRPS)/256, 256>>>(g21, b21, out, 192);
}

// round 8
// speedup vs baseline: 2.4190x; 1.1046x over previous
#include <cuda_runtime.h>
#include <math.h>
#include <stdint.h>

#define BB 16
#define NN 4096
#define MM 1024
#define CF 64
#define INCH 67
#define GRPS (BB*MM)
#define XYZ_OUT ((size_t)BB*MM*3)

// ---------------- device scratch ----------------
__device__ int   g_nbr[(16+32+64)*GRPS];
__device__ float g_x0[(size_t)64 * GRPS * 64];
__device__ float g_rawmax[128 * GRPS];
__device__ float g_rawmin[128 * GRPS];
__device__ float g_stats[512];

__device__ __forceinline__ float sqdist_rn(float dx, float dy, float dz){
    return __fadd_rn(__fadd_rn(__fmul_rn(dx,dx),__fmul_rn(dy,dy)),__fmul_rn(dz,dz));
}
__device__ __forceinline__ float gelu_exact(float x){
    return 0.5f * x * (1.0f + erff(x * 0.70710678118654752f));
}
__device__ __forceinline__ void tf32split(float x, float& hi, float& lo){
    uint32_t h; asm("cvt.rna.tf32.f32 %0, %1;" : "=r"(h) : "f"(x));
    hi = __uint_as_float(h);
    float r = x - hi;
    uint32_t l; asm("cvt.rna.tf32.f32 %0, %1;" : "=r"(l) : "f"(r));
    lo = __uint_as_float(l);
}
__device__ __forceinline__ void mma_tf32(float* d,
    uint32_t a0,uint32_t a1,uint32_t a2,uint32_t a3, uint32_t b0,uint32_t b1){
    asm volatile(
        "mma.sync.aligned.m16n8k8.row.col.f32.tf32.tf32.f32 "
        "{%0,%1,%2,%3}, {%4,%5,%6,%7}, {%8,%9}, {%0,%1,%2,%3};"
        : "+f"(d[0]), "+f"(d[1]), "+f"(d[2]), "+f"(d[3])
        : "r"(a0), "r"(a1), "r"(a2), "r"(a3), "r"(b0), "r"(b1));
}
__device__ __forceinline__ void mma3(float* acc, const float4& ah, const float4& al, const float4& bb){
    mma_tf32(acc, __float_as_uint(ah.x),__float_as_uint(ah.y),__float_as_uint(ah.z),__float_as_uint(ah.w),
                  __float_as_uint(bb.x),__float_as_uint(bb.y));
    mma_tf32(acc, __float_as_uint(ah.x),__float_as_uint(ah.y),__float_as_uint(ah.z),__float_as_uint(ah.w),
                  __float_as_uint(bb.z),__float_as_uint(bb.w));
    mma_tf32(acc, __float_as_uint(al.x),__float_as_uint(al.y),__float_as_uint(al.z),__float_as_uint(al.w),
                  __float_as_uint(bb.x),__float_as_uint(bb.y));
}
// split 8 channel values -> 4 fragment-packed float4s, store contiguously
__device__ __forceinline__ void pack_store(float4* dst, const float* v){
    #pragma unroll
    for (int t=0;t<4;t++){
        float4 fr;
        tf32split(v[t],   fr.x, fr.z);
        tf32split(v[t+4], fr.y, fr.w);
        dst[t]=fr;
    }
}

// ---------------- 1) farthest point sampling (single barrier/iter) ----------------
__global__ void fps_kernel(const float* __restrict__ xyz, float* __restrict__ out_newxyz){
    extern __shared__ float sm[];
    float* sx = sm; float* sy = sm+NN; float* sz = sm+2*NN;
    __shared__ float rv[2][32]; __shared__ int ri[2][32];
    int b = blockIdx.x, t = threadIdx.x, lane = t&31, wid = t>>5;
    for (int i=t;i<NN;i+=blockDim.x){
        const float* p = xyz + ((size_t)b*NN+i)*3;
        sx[i]=p[0]; sy[i]=p[1]; sz[i]=p[2];
    }
    __syncthreads();
    float dreg[4] = {1e10f,1e10f,1e10f,1e10f};
    int far = 0;
    for (int it=0; it<MM; it++){
        float cx=sx[far], cy=sy[far], cz=sz[far];
        if (t==0){
            float* o = out_newxyz + ((size_t)b*MM+it)*3;
            o[0]=cx; o[1]=cy; o[2]=cz;
        }
        float best=-1.0f; int bi=0;
        #pragma unroll
        for (int u=0;u<4;u++){
            int i = t + u*1024;
            float d  = sqdist_rn(sx[i]-cx, sy[i]-cy, sz[i]-cz);
            float nd = fminf(dreg[u], d);
            dreg[u]=nd;
            if (nd>best){ best=nd; bi=i; }
        }
        #pragma unroll
        for (int o=16;o;o>>=1){
            float ov=__shfl_down_sync(0xffffffffu,best,o);
            int   oi=__shfl_down_sync(0xffffffffu,bi,o);
            if (ov>best || (ov==best && oi<bi)){ best=ov; bi=oi; }
        }
        if (lane==0){ rv[it&1][wid]=best; ri[it&1][wid]=bi; }
        __syncthreads();
        // every warp redundantly reduces the 32 per-warp bests (no 2nd barrier;
        // double buffer makes the re-write of a bank 2 barriers after its read)
        float v2 = rv[it&1][lane]; int i2 = ri[it&1][lane];
        #pragma unroll
        for (int o=16;o;o>>=1){
            float ov=__shfl_down_sync(0xffffffffu,v2,o);
            int   oi=__shfl_down_sync(0xffffffffu,i2,o);
            if (ov>v2 || (ov==v2 && oi<i2)){ v2=ov; i2=oi; }
        }
        far = __shfl_sync(0xffffffffu, i2, 0);
    }
}

// ---------------- 2) ball query ----------------
__global__ void __launch_bounds__(256)
ballq_kernel(const float* __restrict__ xyz, const float* __restrict__ newxyz){
    extern __shared__ float sm[];
    float* sx = sm; float* sy = sm+NN; float* sz = sm+2*NN;
    int tid = threadIdx.x;
    int gw0 = blockIdx.x*8;
    int b   = gw0 >> 10;
    const float* base = xyz + (size_t)b*NN*3;
    for (int j=tid;j<NN*3;j+=256){
        float v = base[j];
        int idx = j/3, ch = j-idx*3;
        if (ch==0) sx[idx]=v; else if (ch==1) sy[idx]=v; else sz[idx]=v;
    }
    __syncthreads();
    int w    = tid>>5;
    int lane = tid&31;
    int gw   = gw0 + w;
    float cx=newxyz[gw*3+0], cy=newxyz[gw*3+1], cz=newxyz[gw*3+2];
    const float R2_0=(float)(0.1*0.1), R2_1=(float)(0.2*0.2), R2_2=(float)(0.4*0.4);
    int c0=0,c1=0,c2=0, f0=0,f1=0,f2=0;
    int* n0 = g_nbr + gw*16;
    int* n1 = g_nbr + 16*GRPS + gw*32;
    int* n2 = g_nbr + 48*GRPS + gw*64;
    for (int s=0;s<NN;s+=32){
        int i = s + lane;
        float d = sqdist_rn(sx[i]-cx, sy[i]-cy, sz[i]-cz);
        unsigned m0=__ballot_sync(0xffffffffu, d<=R2_0);
        unsigned m1=__ballot_sync(0xffffffffu, d<=R2_1);
        unsigned m2=__ballot_sync(0xffffffffu, d<=R2_2);
        if (m0 && c0<16){
            if (c0==0) f0 = s + __ffs(m0) - 1;
            int r = __popc(m0 & ((1u<<lane)-1u));
            if ((m0>>lane)&1u){ if (c0+r<16) n0[c0+r]=i; }
            c0 += __popc(m0); if (c0>16) c0=16;
        }
        if (m1 && c1<32){
            if (c1==0) f1 = s + __ffs(m1) - 1;
            int r = __popc(m1 & ((1u<<lane)-1u));
            if ((m1>>lane)&1u){ if (c1+r<32) n1[c1+r]=i; }
            c1 += __popc(m1); if (c1>32) c1=32;
        }
        if (m2 && c2<64){
            if (c2==0) f2 = s + __ffs(m2) - 1;
            int r = __popc(m2 & ((1u<<lane)-1u));
            if ((m2>>lane)&1u){ if (c2+r<64) n2[c2+r]=i; }
            c2 += __popc(m2); if (c2>64) c2=64;
        }
        if (c0>=16 && c1>=32 && c2>=64) break;
    }
    for (int j=c0+lane;j<16;j+=32) n0[j]=f0;
    for (int j=c1+lane;j<32;j+=32) n1[j]=f1;
    for (int j=c2+lane;j<64;j+=32) n2[j]=f2;
}

__global__ void zero_stats_kernel(){ g_stats[threadIdx.x] = 0.0f; }

// ---------------- 3a) pass A: vectorized gather + fragment-packed tf32 mma conv0 ----------------
template<int K,int C0>
__global__ void __launch_bounds__(256)
passA_kernel(const float* __restrict__ xyz, const float* __restrict__ feat,
             const float* __restrict__ newxyz, int noff,
             const float* __restrict__ w0)
{
    const int P = GRPS*K;
    constexpr int KS = 9;                 // 72/8 k-steps
    constexpr int CT = C0/16;
    extern __shared__ float smf[];
    float4* inb4 = (float4*)smf;                 // KS*128*4 fragment-packed input
    float4* wh4  = inb4 + KS*128*4;              // KS*CT*32
    float4* wl4  = wh4 + KS*CT*32;
    float*  st   = (float*)(wl4 + KS*CT*32);     // 2*C0
    int tid = threadIdx.x;
    int tp  = blockIdx.x*128;

    // weight fragments (hi/lo), zero-padded beyond INCH
    for (int i=tid;i<KS*CT*32;i+=256){
        int ks=i/(CT*32), rem=i-ks*CT*32, ct=rem>>5, ln=rem&31;
        int g=ln>>2, t=ln&3, c0=ct*16, k=ks*8;
        float4 H,L; float v;
        v = (k+t  <INCH)? w0[(c0+g  )*INCH + k+t  ] : 0.0f; tf32split(v,H.x,L.x);
        v = (k+t  <INCH)? w0[(c0+g+8)*INCH + k+t  ] : 0.0f; tf32split(v,H.y,L.y);
        v = (k+t+4<INCH)? w0[(c0+g  )*INCH + k+t+4] : 0.0f; tf32split(v,H.z,L.z);
        v = (k+t+4<INCH)? w0[(c0+g+8)*INCH + k+t+4] : 0.0f; tf32split(v,H.w,L.w);
        wh4[i]=H; wl4[i]=L;
    }
    for (int i=tid;i<2*C0;i+=256) st[i]=0.0f;

    { // gather: 2 threads per point; h0 owns ks 0-3 (ch 0-31), h1 owns ks 4-8 (ch 32-71)
        int p  = tid>>1, h = tid&1;
        int gp = tp + p;
        int g  = gp / K;
        int idx = g_nbr[noff + gp];
        int b   = g >> 10;
        const float* fs = feat + ((size_t)(b*NN)+idx)*CF;
        if (h==0){
            const float* xs = xyz + ((size_t)(b*NN)+idx)*3;
            float ch[32];
            ch[0]=xs[0]-newxyz[g*3+0];
            ch[1]=xs[1]-newxyz[g*3+1];
            ch[2]=xs[2]-newxyz[g*3+2];
            #pragma unroll
            for (int q=0;q<7;q++){
                float4 v = *(const float4*)(fs + q*4);
                ch[3+q*4+0]=v.x; ch[3+q*4+1]=v.y; ch[3+q*4+2]=v.z; ch[3+q*4+3]=v.w;
            }
            ch[31]=fs[28];
            #pragma unroll
            for (int ks=0;ks<4;ks++)
                pack_store(inb4 + (((ks<<7)+p)<<2), ch+ks*8);
        } else {
            float cch[40];   // cch[j] = channel 32+j = feat[29+j], zero for j>=35
            { float4 v = *(const float4*)(fs + 28); cch[0]=v.y; cch[1]=v.z; cch[2]=v.w; }
            #pragma unroll
            for (int q=1;q<9;q++){
                float4 v = *(const float4*)(fs + 28 + q*4);
                cch[4*q-1]=v.x; cch[4*q]=v.y; cch[4*q+1]=v.z; cch[4*q+2]=v.w;
            }
            #pragma unroll
            for (int j=35;j<40;j++) cch[j]=0.0f;
            #pragma unroll
            for (int ks=4;ks<9;ks++)
                pack_store(inb4 + (((ks<<7)+p)<<2), cch+(ks-4)*8);
        }
    }
    __syncthreads();

    constexpr int PG = 8/CT;
    constexpr int PW = 128/PG;
    constexpr int NT = PW/8;
    int ln = tid&31, w = tid>>5;
    int g = ln>>2, t = ln&3;
    int ct = w%CT;
    int ch0 = ct*16;
    int pb  = (w/CT)*PW;

    float acc[NT][4];
    #pragma unroll
    for (int nt=0;nt<NT;nt++){ acc[nt][0]=0;acc[nt][1]=0;acc[nt][2]=0;acc[nt][3]=0; }

    for (int ks=0; ks<KS; ks++){
        float4 ah = wh4[(ks*CT+ct)*32+ln];
        float4 al = wl4[(ks*CT+ct)*32+ln];
        #pragma unroll
        for (int nt=0;nt<NT;nt++){
            float4 bb = inb4[((ks<<7) + pb + nt*8 + g)*4 + t];
            mma3(acc[nt], ah, al, bb);
        }
    }

    float sA=0,sA2=0,sB=0,sB2=0;
    #pragma unroll
    for (int nt=0;nt<NT;nt++){
        float x=acc[nt][0], y=acc[nt][1], z=acc[nt][2], v=acc[nt][3];
        sA += x+y; sA2 += x*x+y*y; sB += z+v; sB2 += z*z+v*v;
        int pofs = tp + pb + nt*8 + 2*t;
        *(float2*)(g_x0 + (size_t)(ch0+g)*P   + pofs) = make_float2(x,y);
        *(float2*)(g_x0 + (size_t)(ch0+g+8)*P + pofs) = make_float2(z,v);
    }
    #pragma unroll
    for (int o=1;o<4;o<<=1){
        sA  += __shfl_xor_sync(0xffffffffu,sA,o);
        sA2 += __shfl_xor_sync(0xffffffffu,sA2,o);
        sB  += __shfl_xor_sync(0xffffffffu,sB,o);
        sB2 += __shfl_xor_sync(0xffffffffu,sB2,o);
    }
    if (t==0){
        atomicAdd(&st[ch0+g],      sA);  atomicAdd(&st[C0+ch0+g],   sA2);
        atomicAdd(&st[ch0+g+8],    sB);  atomicAdd(&st[C0+ch0+g+8], sB2);
    }
    __syncthreads();
    for (int i=tid;i<C0;i+=256){
        atomicAdd(&g_stats[i],     st[i]);
        atomicAdd(&g_stats[128+i], st[C0+i]);
    }
}

// ---------------- 3b) pass C: vectorized norm+gelu fill -> fragment-packed tf32 mma conv1 ----------------
template<int K,int C0,int C1,int PTS,int NTH>
__global__ void __launch_bounds__(NTH)
passC_kernel(const float* __restrict__ w1,
             const float* __restrict__ g0v, const float* __restrict__ b0v)
{
    const int P = GRPS*K;
    constexpr int KS = C0/8;
    constexpr int CT = C1/16;
    extern __shared__ float smf[];
    float4* gsb4 = (float4*)smf;                 // KS*PTS*4
    float4* wh4  = gsb4 + KS*PTS*4;              // KS*CT*32
    float4* wl4  = wh4 + KS*CT*32;
    float*  ab   = (float*)(wl4 + KS*CT*32);     // 2*C0
    float*  st   = ab + 2*C0;                    // 2*C1
    int tid = threadIdx.x, tp = blockIdx.x*PTS;

    if (tid < C0){
        float cnt  = (float)P;
        float mean = g_stats[tid]/cnt;
        float var  = g_stats[128+tid]/cnt - mean*mean;
        float a    = g0v[tid]/sqrtf(var + 1e-5f);
        ab[tid]    = a;
        ab[C0+tid] = b0v[tid] - mean*a;
    }
    for (int i=tid;i<KS*CT*32;i+=NTH){
        int ks=i/(CT*32), rem=i-ks*CT*32, ct=rem>>5, ln=rem&31;
        int g=ln>>2, t=ln&3, c0=ct*16, k=ks*8;
        float4 H,L;
        tf32split(w1[(c0+g  )*C0 + k+t  ], H.x, L.x);
        tf32split(w1[(c0+g+8)*C0 + k+t  ], H.y, L.y);
        tf32split(w1[(c0+g  )*C0 + k+t+4], H.z, L.z);
        tf32split(w1[(c0+g+8)*C0 + k+t+4], H.w, L.w);
        wh4[i]=H; wl4[i]=L;
    }
    for (int i=tid;i<2*C1;i+=NTH) st[i]=0.0f;
    __syncthreads();

    // norm+gelu fill: thread owns (ks, p): 8 coalesced loads -> 4 STS.128
    for (int task=tid; task<KS*PTS; task+=NTH){
        int ks=task/PTS, p=task-ks*PTS;
        float ch[8];
        #pragma unroll
        for (int j=0;j<8;j++){
            int c=ks*8+j;
            float v = g_x0[(size_t)c*P + tp + p];
            ch[j] = gelu_exact(ab[c]*v + ab[C0+c]);
        }
        pack_store(gsb4 + ((ks*PTS+p)<<2), ch);
    }
    __syncthreads();

    constexpr int NW = NTH/32;
    constexpr int PG = NW/CT;
    constexpr int PW = PTS/PG;
    constexpr int NT = PW/8;
    int ln = tid&31, w = tid>>5;
    int g = ln>>2, t = ln&3;
    int ct = w%CT;
    int ch0 = ct*16;
    int pb  = (w/CT)*PW;

    float acc[NT][4];
    #pragma unroll
    for (int nt=0;nt<NT;nt++){ acc[nt][0]=0;acc[nt][1]=0;acc[nt][2]=0;acc[nt][3]=0; }

    for (int ks=0; ks<KS; ks++){
        float4 ah = wh4[(ks*CT+ct)*32+ln];
        float4 al = wl4[(ks*CT+ct)*32+ln];
        #pragma unroll
        for (int nt=0;nt<NT;nt++){
            float4 bb = gsb4[(ks*PTS + pb + nt*8 + g)*4 + t];
            mma3(acc[nt], ah, al, bb);
        }
    }

    float sA=0,sA2=0,sB=0,sB2=0;
    #pragma unroll
    for (int nt=0;nt<NT;nt++){
        float x=acc[nt][0], y=acc[nt][1], z=acc[nt][2], v=acc[nt][3];
        sA += x+y; sA2 += x*x+y*y; sB += z+v; sB2 += z*z+v*v;
    }
    #pragma unroll
    for (int o=1;o<4;o<<=1){
        sA  += __shfl_xor_sync(0xffffffffu,sA,o);
        sA2 += __shfl_xor_sync(0xffffffffu,sA2,o);
        sB  += __shfl_xor_sync(0xffffffffu,sB,o);
        sB2 += __shfl_xor_sync(0xffffffffu,sB2,o);
    }
    if (t==0){
        atomicAdd(&st[ch0+g],      sA);  atomicAdd(&st[C1+ch0+g],   sA2);
        atomicAdd(&st[ch0+g+8],    sB);  atomicAdd(&st[C1+ch0+g+8], sB2);
    }

    constexpr int NTPG = K/8;
    constexpr int NG   = NT/NTPG;
    int gbase = (tp + pb)/K;
    #pragma unroll
    for (int gi=0; gi<NG; gi++){
        float mxA=-3.4e38f, mnA=3.4e38f, mxB=-3.4e38f, mnB=3.4e38f;
        #pragma unroll
        for (int u=0; u<NTPG; u++){
            float* a = acc[gi*NTPG+u];
            mxA=fmaxf(mxA,fmaxf(a[0],a[1])); mnA=fminf(mnA,fminf(a[0],a[1]));
            mxB=fmaxf(mxB,fmaxf(a[2],a[3])); mnB=fminf(mnB,fminf(a[2],a[3]));
        }
        #pragma unroll
        for (int o=1;o<4;o<<=1){
            mxA=fmaxf(mxA,__shfl_xor_sync(0xffffffffu,mxA,o));
            mnA=fminf(mnA,__shfl_xor_sync(0xffffffffu,mnA,o));
            mxB=fmaxf(mxB,__shfl_xor_sync(0xffffffffu,mxB,o));
            mnB=fminf(mnB,__shfl_xor_sync(0xffffffffu,mnB,o));
        }
        if (t==0){
            int gg = gbase + gi;
            g_rawmax[(ch0+g)*GRPS   + gg] = mxA;  g_rawmin[(ch0+g)*GRPS   + gg] = mnA;
            g_rawmax[(ch0+g+8)*GRPS + gg] = mxB;  g_rawmin[(ch0+g+8)*GRPS + gg] = mnB;
        }
    }
    __syncthreads();
    for (int i=tid;i<C1;i+=NTH){
        atomicAdd(&g_stats[256+i], st[i]);
        atomicAdd(&g_stats[384+i], st[C1+i]);
    }
}

// ---------------- 3c) finalize ----------------
template<int K,int C1>
__global__ void out_kernel(const float* __restrict__ g1v, const float* __restrict__ b1v,
                           float* __restrict__ out, int chOff)
{
    int i = blockIdx.x*blockDim.x + threadIdx.x;
    if (i >= C1*GRPS) return;
    int c = i / GRPS; int g = i - c*GRPS;
    int b = g >> 10, m = g & 1023;
    float cnt  = (float)(GRPS*K);
    float mean = g_stats[256+c]/cnt;
    float var  = g_stats[384+c]/cnt - mean*mean;
    float a    = g1v[c]/sqrtf(var + 1e-5f);
    float bb   = b1v[c] - mean*a;
    float v1   = a*g_rawmax[c*GRPS + g] + bb;
    float v2   = a*g_rawmin[c*GRPS + g] + bb;
    out[XYZ_OUT + ((size_t)b*320 + chOff + c)*MM + m] = fmaxf(gelu_exact(v1), gelu_exact(v2));
}

// ---------------- launch ----------------
extern "C" void kernel_launch(void* const* d_in, const int* in_sizes, int n_in,
                              void* d_out, int out_size)
{
    const float* xyz  = (const float*)d_in[0];
    const float* feat = (const float*)d_in[1];
    const float* w00  = (const float*)d_in[2];
    const float* w01  = (const float*)d_in[3];
    const float* w10  = (const float*)d_in[4];
    const float* w11  = (const float*)d_in[5];
    const float* w20  = (const float*)d_in[6];
    const float* w21  = (const float*)d_in[7];
    const float* g00  = (const float*)d_in[8];
    const float* b00  = (const float*)d_in[9];
    const float* g01  = (const float*)d_in[10];
    const float* b01  = (const float*)d_in[11];
    const float* g10  = (const float*)d_in[12];
    const float* b10  = (const float*)d_in[13];
    const float* g11  = (const float*)d_in[14];
    const float* b11  = (const float*)d_in[15];
    const float* g20  = (const float*)d_in[16];
    const float* b20  = (const float*)d_in[17];
    const float* g21  = (const float*)d_in[18];
    const float* b21  = (const float*)d_in[19];
    float* out = (float*)d_out;
    float* newxyz = out;

    const int smFPS = 3*NN*4;
    const int smBQ  = 3*NN*4;
    const int smA32 = (9*128*4 + 2*9*2*32)*16 + 2*32*4;
    const int smA64 = (9*128*4 + 2*9*4*32)*16 + 2*64*4;
    const int smC0  = (4*128*4 + 2*4*4*32)*16 + (2*32 + 2*64)*4;
    const int smC12 = (8*256*4 + 2*8*8*32)*16 + (2*64 + 2*128)*4;

    cudaFuncSetAttribute(fps_kernel,          cudaFuncAttributeMaxDynamicSharedMemorySize, smFPS);
    cudaFuncSetAttribute(ballq_kernel,        cudaFuncAttributeMaxDynamicSharedMemorySize, smBQ);
    cudaFuncSetAttribute(passA_kernel<16,32>, cudaFuncAttributeMaxDynamicSharedMemorySize, smA32);
    cudaFuncSetAttribute(passA_kernel<32,64>, cudaFuncAttributeMaxDynamicSharedMemorySize, smA64);
    cudaFuncSetAttribute(passA_kernel<64,64>, cudaFuncAttributeMaxDynamicSharedMemorySize, smA64);
    cudaFuncSetAttribute(passC_kernel<16,32,64,128,256>,  cudaFuncAttributeMaxDynamicSharedMemorySize, smC0);
    cudaFuncSetAttribute(passC_kernel<32,64,128,256,512>, cudaFuncAttributeMaxDynamicSharedMemorySize, smC12);
    cudaFuncSetAttribute(passC_kernel<64,64,128,256,512>, cudaFuncAttributeMaxDynamicSharedMemorySize, smC12);

    fps_kernel<<<BB, 1024, smFPS>>>(xyz, newxyz);
    ballq_kernel<<<GRPS/8, 256, smBQ>>>(xyz, newxyz);

    // scale 0: k=16, C0=32, C1=64
    zero_stats_kernel<<<1,512>>>();
    passA_kernel<16,32><<<GRPS*16/128, 256, smA32>>>(xyz, feat, newxyz, 0, w00);
    passC_kernel<16,32,64,128,256><<<GRPS*16/128, 256, smC0>>>(w01, g00, b00);
    out_kernel<16,64><<<(64*GRPS)/256, 256>>>(g01, b01, out, 0);

    // scale 1: k=32, C0=64, C1=128
    zero_stats_kernel<<<1,512>>>();
    passA_kernel<32,64><<<GRPS*32/128, 256, smA64>>>(xyz, feat, newxyz, 16*GRPS, w10);
    passC_kernel<32,64,128,256,512><<<GRPS*32/256, 512, smC12>>>(w11, g10, b10);
    out_kernel<32,128><<<(128*GRPS)/256, 256>>>(g11, b11, out, 64);

    // scale 2: k=64, C0=64, C1=128
    zero_stats_kernel<<<1,512>>>();
    passA_kernel<64,64><<<GRPS*64/128, 256, smA64>>>(xyz, feat, newxyz, 48*GRPS, w20);
    passC_kernel<64,64,128,256,512><<<GRPS*64/256, 512, smC12>>>(w21, g20, b20);
    out_kernel<64,128><<<(128*GRPS)/256, 256>>>(g21, b21, out, 192);
}

// round 9
// speedup vs baseline: 2.4302x; 1.0046x over previous
#include <cuda_runtime.h>
#include <math.h>
#include <stdint.h>

#define BB 16
#define NN 4096
#define MM 1024
#define CF 64
#define INCH 67
#define GRPS (BB*MM)
#define XYZ_OUT ((size_t)BB*MM*3)

// ---------------- device scratch ----------------
__device__ int   g_nbr[(16+32+64)*GRPS];
__device__ float g_x0[(size_t)64 * GRPS * 64];
__device__ float g_rawmax[128 * GRPS];
__device__ float g_rawmin[128 * GRPS];
__device__ float g_stats[512];

__device__ __forceinline__ float sqdist_rn(float dx, float dy, float dz){
    return __fadd_rn(__fadd_rn(__fmul_rn(dx,dx),__fmul_rn(dy,dy)),__fmul_rn(dz,dz));
}
__device__ __forceinline__ float gelu_exact(float x){
    return 0.5f * x * (1.0f + erff(x * 0.70710678118654752f));
}
__device__ __forceinline__ void tf32split(float x, float& hi, float& lo){
    uint32_t h; asm("cvt.rna.tf32.f32 %0, %1;" : "=r"(h) : "f"(x));
    hi = __uint_as_float(h);
    float r = x - hi;
    uint32_t l; asm("cvt.rna.tf32.f32 %0, %1;" : "=r"(l) : "f"(r));
    lo = __uint_as_float(l);
}
__device__ __forceinline__ void mma_tf32(float* d,
    uint32_t a0,uint32_t a1,uint32_t a2,uint32_t a3, uint32_t b0,uint32_t b1){
    asm volatile(
        "mma.sync.aligned.m16n8k8.row.col.f32.tf32.tf32.f32 "
        "{%0,%1,%2,%3}, {%4,%5,%6,%7}, {%8,%9}, {%0,%1,%2,%3};"
        : "+f"(d[0]), "+f"(d[1]), "+f"(d[2]), "+f"(d[3])
        : "r"(a0), "r"(a1), "r"(a2), "r"(a3), "r"(b0), "r"(b1));
}
__device__ __forceinline__ void mma3(float* acc, const float4& ah, const float4& al, const float4& bb){
    mma_tf32(acc, __float_as_uint(ah.x),__float_as_uint(ah.y),__float_as_uint(ah.z),__float_as_uint(ah.w),
                  __float_as_uint(bb.x),__float_as_uint(bb.y));
    mma_tf32(acc, __float_as_uint(ah.x),__float_as_uint(ah.y),__float_as_uint(ah.z),__float_as_uint(ah.w),
                  __float_as_uint(bb.z),__float_as_uint(bb.w));
    mma_tf32(acc, __float_as_uint(al.x),__float_as_uint(al.y),__float_as_uint(al.z),__float_as_uint(al.w),
                  __float_as_uint(bb.x),__float_as_uint(bb.y));
}
// split 8 channel values -> 4 fragment-packed float4s, store contiguously
__device__ __forceinline__ void pack_store(float4* dst, const float* v){
    #pragma unroll
    for (int t=0;t<4;t++){
        float4 fr;
        tf32split(v[t],   fr.x, fr.z);
        tf32split(v[t+4], fr.y, fr.w);
        dst[t]=fr;
    }
}

// ---------------- 1) farthest point sampling (single barrier/iter) ----------------
__global__ void fps_kernel(const float* __restrict__ xyz, float* __restrict__ out_newxyz){
    extern __shared__ float sm[];
    float* sx = sm; float* sy = sm+NN; float* sz = sm+2*NN;
    __shared__ float rv[2][32]; __shared__ int ri[2][32];
    int b = blockIdx.x, t = threadIdx.x, lane = t&31, wid = t>>5;
    for (int i=t;i<NN;i+=blockDim.x){
        const float* p = xyz + ((size_t)b*NN+i)*3;
        sx[i]=p[0]; sy[i]=p[1]; sz[i]=p[2];
    }
    __syncthreads();
    float dreg[4] = {1e10f,1e10f,1e10f,1e10f};
    int far = 0;
    for (int it=0; it<MM; it++){
        float cx=sx[far], cy=sy[far], cz=sz[far];
        if (t==0){
            float* o = out_newxyz + ((size_t)b*MM+it)*3;
            o[0]=cx; o[1]=cy; o[2]=cz;
        }
        float best=-1.0f; int bi=0;
        #pragma unroll
        for (int u=0;u<4;u++){
            int i = t + u*1024;
            float d  = sqdist_rn(sx[i]-cx, sy[i]-cy, sz[i]-cz);
            float nd = fminf(dreg[u], d);
            dreg[u]=nd;
            if (nd>best){ best=nd; bi=i; }
        }
        #pragma unroll
        for (int o=16;o;o>>=1){
            float ov=__shfl_down_sync(0xffffffffu,best,o);
            int   oi=__shfl_down_sync(0xffffffffu,bi,o);
            if (ov>best || (ov==best && oi<bi)){ best=ov; bi=oi; }
        }
        if (lane==0){ rv[it&1][wid]=best; ri[it&1][wid]=bi; }
        __syncthreads();
        float v2 = rv[it&1][lane]; int i2 = ri[it&1][lane];
        #pragma unroll
        for (int o=16;o;o>>=1){
            float ov=__shfl_down_sync(0xffffffffu,v2,o);
            int   oi=__shfl_down_sync(0xffffffffu,i2,o);
            if (ov>v2 || (ov==v2 && oi<i2)){ v2=ov; i2=oi; }
        }
        far = __shfl_sync(0xffffffffu, i2, 0);
    }
}

// ---------------- 2) ball query ----------------
__global__ void __launch_bounds__(256)
ballq_kernel(const float* __restrict__ xyz, const float* __restrict__ newxyz){
    extern __shared__ float sm[];
    float* sx = sm; float* sy = sm+NN; float* sz = sm+2*NN;
    int tid = threadIdx.x;
    int gw0 = blockIdx.x*8;
    int b   = gw0 >> 10;
    const float* base = xyz + (size_t)b*NN*3;
    for (int j=tid;j<NN*3;j+=256){
        float v = base[j];
        int idx = j/3, ch = j-idx*3;
        if (ch==0) sx[idx]=v; else if (ch==1) sy[idx]=v; else sz[idx]=v;
    }
    __syncthreads();
    int w    = tid>>5;
    int lane = tid&31;
    int gw   = gw0 + w;
    float cx=newxyz[gw*3+0], cy=newxyz[gw*3+1], cz=newxyz[gw*3+2];
    const float R2_0=(float)(0.1*0.1), R2_1=(float)(0.2*0.2), R2_2=(float)(0.4*0.4);
    int c0=0,c1=0,c2=0, f0=0,f1=0,f2=0;
    int* n0 = g_nbr + gw*16;
    int* n1 = g_nbr + 16*GRPS + gw*32;
    int* n2 = g_nbr + 48*GRPS + gw*64;
    for (int s=0;s<NN;s+=32){
        int i = s + lane;
        float d = sqdist_rn(sx[i]-cx, sy[i]-cy, sz[i]-cz);
        unsigned m0=__ballot_sync(0xffffffffu, d<=R2_0);
        unsigned m1=__ballot_sync(0xffffffffu, d<=R2_1);
        unsigned m2=__ballot_sync(0xffffffffu, d<=R2_2);
        if (m0 && c0<16){
            if (c0==0) f0 = s + __ffs(m0) - 1;
            int r = __popc(m0 & ((1u<<lane)-1u));
            if ((m0>>lane)&1u){ if (c0+r<16) n0[c0+r]=i; }
            c0 += __popc(m0); if (c0>16) c0=16;
        }
        if (m1 && c1<32){
            if (c1==0) f1 = s + __ffs(m1) - 1;
            int r = __popc(m1 & ((1u<<lane)-1u));
            if ((m1>>lane)&1u){ if (c1+r<32) n1[c1+r]=i; }
            c1 += __popc(m1); if (c1>32) c1=32;
        }
        if (m2 && c2<64){
            if (c2==0) f2 = s + __ffs(m2) - 1;
            int r = __popc(m2 & ((1u<<lane)-1u));
            if ((m2>>lane)&1u){ if (c2+r<64) n2[c2+r]=i; }
            c2 += __popc(m2); if (c2>64) c2=64;
        }
        if (c0>=16 && c1>=32 && c2>=64) break;
    }
    for (int j=c0+lane;j<16;j+=32) n0[j]=f0;
    for (int j=c1+lane;j<32;j+=32) n1[j]=f1;
    for (int j=c2+lane;j<64;j+=32) n2[j]=f2;
}

__global__ void zero_stats_kernel(){ g_stats[threadIdx.x] = 0.0f; }

// ---------------- 3a) pass A: gather + dual-tile tf32 mma conv0 ----------------
template<int K,int C0>
__global__ void __launch_bounds__(256)
passA_kernel(const float* __restrict__ xyz, const float* __restrict__ feat,
             const float* __restrict__ newxyz, int noff,
             const float* __restrict__ w0)
{
    const int P = GRPS*K;
    constexpr int KS = 9;
    constexpr int CT = C0/16;
    extern __shared__ float smf[];
    float4* inb4 = (float4*)smf;                 // KS*128*4
    float4* wh4  = inb4 + KS*128*4;              // KS*CT*32
    float4* wl4  = wh4 + KS*CT*32;
    float*  st   = (float*)(wl4 + KS*CT*32);     // 2*C0
    int tid = threadIdx.x;
    int tp  = blockIdx.x*128;

    for (int i=tid;i<KS*CT*32;i+=256){
        int ks=i/(CT*32), rem=i-ks*CT*32, ct=rem>>5, ln=rem&31;
        int g=ln>>2, t=ln&3, c0=ct*16, k=ks*8;
        float4 H,L; float v;
        v = (k+t  <INCH)? w0[(c0+g  )*INCH + k+t  ] : 0.0f; tf32split(v,H.x,L.x);
        v = (k+t  <INCH)? w0[(c0+g+8)*INCH + k+t  ] : 0.0f; tf32split(v,H.y,L.y);
        v = (k+t+4<INCH)? w0[(c0+g  )*INCH + k+t+4] : 0.0f; tf32split(v,H.z,L.z);
        v = (k+t+4<INCH)? w0[(c0+g+8)*INCH + k+t+4] : 0.0f; tf32split(v,H.w,L.w);
        wh4[i]=H; wl4[i]=L;
    }
    for (int i=tid;i<2*C0;i+=256) st[i]=0.0f;

    { // gather: 2 threads per point; h0 owns ks 0-3 (ch 0-31), h1 owns ks 4-8
        int p  = tid>>1, h = tid&1;
        int gp = tp + p;
        int g  = gp / K;
        int idx = g_nbr[noff + gp];
        int b   = g >> 10;
        const float* fs = feat + ((size_t)(b*NN)+idx)*CF;
        if (h==0){
            const float* xs = xyz + ((size_t)(b*NN)+idx)*3;
            float ch[32];
            ch[0]=xs[0]-newxyz[g*3+0];
            ch[1]=xs[1]-newxyz[g*3+1];
            ch[2]=xs[2]-newxyz[g*3+2];
            #pragma unroll
            for (int q=0;q<7;q++){
                float4 v = *(const float4*)(fs + q*4);
                ch[3+q*4+0]=v.x; ch[3+q*4+1]=v.y; ch[3+q*4+2]=v.z; ch[3+q*4+3]=v.w;
            }
            ch[31]=fs[28];
            #pragma unroll
            for (int ks=0;ks<4;ks++)
                pack_store(inb4 + (((ks<<7)+p)<<2), ch+ks*8);
        } else {
            float cch[40];
            { float4 v = *(const float4*)(fs + 28); cch[0]=v.y; cch[1]=v.z; cch[2]=v.w; }
            #pragma unroll
            for (int q=1;q<9;q++){
                float4 v = *(const float4*)(fs + 28 + q*4);
                cch[4*q-1]=v.x; cch[4*q]=v.y; cch[4*q+1]=v.z; cch[4*q+2]=v.w;
            }
            #pragma unroll
            for (int j=35;j<40;j++) cch[j]=0.0f;
            #pragma unroll
            for (int ks=4;ks<9;ks++)
                pack_store(inb4 + (((ks<<7)+p)<<2), cch+(ks-4)*8);
        }
    }
    __syncthreads();

    constexpr int CT2 = CT/2;          // warp channel-pairs
    constexpr int PG2 = 8/CT2;
    constexpr int PW  = 128/PG2;
    constexpr int NT  = PW/8;
    int ln = tid&31, w = tid>>5;
    int g = ln>>2, t = ln&3;
    int ct2 = w%CT2;
    int pb  = (w/CT2)*PW;

    float acc[2][NT][4];
    #pragma unroll
    for (int cc=0;cc<2;cc++)
        #pragma unroll
        for (int nt=0;nt<NT;nt++){ acc[cc][nt][0]=0;acc[cc][nt][1]=0;acc[cc][nt][2]=0;acc[cc][nt][3]=0; }

    for (int ks=0; ks<KS; ks++){
        float4 ah0 = wh4[(ks*CT+ct2*2  )*32+ln];
        float4 al0 = wl4[(ks*CT+ct2*2  )*32+ln];
        float4 ah1 = wh4[(ks*CT+ct2*2+1)*32+ln];
        float4 al1 = wl4[(ks*CT+ct2*2+1)*32+ln];
        #pragma unroll
        for (int nt=0;nt<NT;nt++){
            float4 bb = inb4[((ks<<7) + pb + nt*8 + g)*4 + t];
            mma3(acc[0][nt], ah0, al0, bb);
            mma3(acc[1][nt], ah1, al1, bb);
        }
    }

    #pragma unroll
    for (int cc=0;cc<2;cc++){
        int ch0 = (ct2*2+cc)*16;
        float sA=0,sA2=0,sB=0,sB2=0;
        #pragma unroll
        for (int nt=0;nt<NT;nt++){
            float x=acc[cc][nt][0], y=acc[cc][nt][1], z=acc[cc][nt][2], v=acc[cc][nt][3];
            sA += x+y; sA2 += x*x+y*y; sB += z+v; sB2 += z*z+v*v;
            int pofs = tp + pb + nt*8 + 2*t;
            *(float2*)(g_x0 + (size_t)(ch0+g)*P   + pofs) = make_float2(x,y);
            *(float2*)(g_x0 + (size_t)(ch0+g+8)*P + pofs) = make_float2(z,v);
        }
        #pragma unroll
        for (int o=1;o<4;o<<=1){
            sA  += __shfl_xor_sync(0xffffffffu,sA,o);
            sA2 += __shfl_xor_sync(0xffffffffu,sA2,o);
            sB  += __shfl_xor_sync(0xffffffffu,sB,o);
            sB2 += __shfl_xor_sync(0xffffffffu,sB2,o);
        }
        if (t==0){
            atomicAdd(&st[ch0+g],      sA);  atomicAdd(&st[C0+ch0+g],   sA2);
            atomicAdd(&st[ch0+g+8],    sB);  atomicAdd(&st[C0+ch0+g+8], sB2);
        }
    }
    __syncthreads();
    for (int i=tid;i<C0;i+=256){
        atomicAdd(&g_stats[i],     st[i]);
        atomicAdd(&g_stats[128+i], st[C0+i]);
    }
}

// ---------------- 3b) pass C: norm+gelu fill -> dual-tile tf32 mma conv1 ----------------
template<int K,int C0,int C1,int PTS,int NTH>
__global__ void __launch_bounds__(NTH)
passC_kernel(const float* __restrict__ w1,
             const float* __restrict__ g0v, const float* __restrict__ b0v)
{
    const int P = GRPS*K;
    constexpr int KS = C0/8;
    constexpr int CT = C1/16;
    extern __shared__ float smf[];
    float4* gsb4 = (float4*)smf;                 // KS*PTS*4
    float4* wh4  = gsb4 + KS*PTS*4;              // KS*CT*32
    float4* wl4  = wh4 + KS*CT*32;
    float*  ab   = (float*)(wl4 + KS*CT*32);     // 2*C0
    float*  st   = ab + 2*C0;                    // 2*C1
    int tid = threadIdx.x, tp = blockIdx.x*PTS;

    if (tid < C0){
        float cnt  = (float)P;
        float mean = g_stats[tid]/cnt;
        float var  = g_stats[128+tid]/cnt - mean*mean;
        float a    = g0v[tid]/sqrtf(var + 1e-5f);
        ab[tid]    = a;
        ab[C0+tid] = b0v[tid] - mean*a;
    }
    for (int i=tid;i<KS*CT*32;i+=NTH){
        int ks=i/(CT*32), rem=i-ks*CT*32, ct=rem>>5, ln=rem&31;
        int g=ln>>2, t=ln&3, c0=ct*16, k=ks*8;
        float4 H,L;
        tf32split(w1[(c0+g  )*C0 + k+t  ], H.x, L.x);
        tf32split(w1[(c0+g+8)*C0 + k+t  ], H.y, L.y);
        tf32split(w1[(c0+g  )*C0 + k+t+4], H.z, L.z);
        tf32split(w1[(c0+g+8)*C0 + k+t+4], H.w, L.w);
        wh4[i]=H; wl4[i]=L;
    }
    for (int i=tid;i<2*C1;i+=NTH) st[i]=0.0f;
    __syncthreads();

    for (int task=tid; task<KS*PTS; task+=NTH){
        int ks=task/PTS, p=task-ks*PTS;
        float ch[8];
        #pragma unroll
        for (int j=0;j<8;j++){
            int c=ks*8+j;
            float v = g_x0[(size_t)c*P + tp + p];
            ch[j] = gelu_exact(ab[c]*v + ab[C0+c]);
        }
        pack_store(gsb4 + ((ks*PTS+p)<<2), ch);
    }
    __syncthreads();

    constexpr int NW  = NTH/32;
    constexpr int CT2 = CT/2;
    constexpr int PG2 = NW/CT2;
    constexpr int PW  = PTS/PG2;
    constexpr int NT  = PW/8;
    int ln = tid&31, w = tid>>5;
    int g = ln>>2, t = ln&3;
    int ct2 = w%CT2;
    int pb  = (w/CT2)*PW;

    float acc[2][NT][4];
    #pragma unroll
    for (int cc=0;cc<2;cc++)
        #pragma unroll
        for (int nt=0;nt<NT;nt++){ acc[cc][nt][0]=0;acc[cc][nt][1]=0;acc[cc][nt][2]=0;acc[cc][nt][3]=0; }

    for (int ks=0; ks<KS; ks++){
        float4 ah0 = wh4[(ks*CT+ct2*2  )*32+ln];
        float4 al0 = wl4[(ks*CT+ct2*2  )*32+ln];
        float4 ah1 = wh4[(ks*CT+ct2*2+1)*32+ln];
        float4 al1 = wl4[(ks*CT+ct2*2+1)*32+ln];
        #pragma unroll
        for (int nt=0;nt<NT;nt++){
            float4 bb = gsb4[(ks*PTS + pb + nt*8 + g)*4 + t];
            mma3(acc[0][nt], ah0, al0, bb);
            mma3(acc[1][nt], ah1, al1, bb);
        }
    }

    constexpr int NTPG = K/8;
    constexpr int NG   = NT/NTPG;
    int gbase = (tp + pb)/K;
    #pragma unroll
    for (int cc=0;cc<2;cc++){
        int ch0 = (ct2*2+cc)*16;
        float sA=0,sA2=0,sB=0,sB2=0;
        #pragma unroll
        for (int nt=0;nt<NT;nt++){
            float x=acc[cc][nt][0], y=acc[cc][nt][1], z=acc[cc][nt][2], v=acc[cc][nt][3];
            sA += x+y; sA2 += x*x+y*y; sB += z+v; sB2 += z*z+v*v;
        }
        #pragma unroll
        for (int o=1;o<4;o<<=1){
            sA  += __shfl_xor_sync(0xffffffffu,sA,o);
            sA2 += __shfl_xor_sync(0xffffffffu,sA2,o);
            sB  += __shfl_xor_sync(0xffffffffu,sB,o);
            sB2 += __shfl_xor_sync(0xffffffffu,sB2,o);
        }
        if (t==0){
            atomicAdd(&st[ch0+g],      sA);  atomicAdd(&st[C1+ch0+g],   sA2);
            atomicAdd(&st[ch0+g+8],    sB);  atomicAdd(&st[C1+ch0+g+8], sB2);
        }
        #pragma unroll
        for (int gi=0; gi<NG; gi++){
            float mxA=-3.4e38f, mnA=3.4e38f, mxB=-3.4e38f, mnB=3.4e38f;
            #pragma unroll
            for (int u=0; u<NTPG; u++){
                float* a = acc[cc][gi*NTPG+u];
                mxA=fmaxf(mxA,fmaxf(a[0],a[1])); mnA=fminf(mnA,fminf(a[0],a[1]));
                mxB=fmaxf(mxB,fmaxf(a[2],a[3])); mnB=fminf(mnB,fminf(a[2],a[3]));
            }
            #pragma unroll
            for (int o=1;o<4;o<<=1){
                mxA=fmaxf(mxA,__shfl_xor_sync(0xffffffffu,mxA,o));
                mnA=fminf(mnA,__shfl_xor_sync(0xffffffffu,mnA,o));
                mxB=fmaxf(mxB,__shfl_xor_sync(0xffffffffu,mxB,o));
                mnB=fminf(mnB,__shfl_xor_sync(0xffffffffu,mnB,o));
            }
            if (t==0){
                int gg = gbase + gi;
                g_rawmax[(ch0+g)*GRPS   + gg] = mxA;  g_rawmin[(ch0+g)*GRPS   + gg] = mnA;
                g_rawmax[(ch0+g+8)*GRPS + gg] = mxB;  g_rawmin[(ch0+g+8)*GRPS + gg] = mnB;
            }
        }
    }
    __syncthreads();
    for (int i=tid;i<C1;i+=NTH){
        atomicAdd(&g_stats[256+i], st[i]);
        atomicAdd(&g_stats[384+i], st[C1+i]);
    }
}

// ---------------- 3c) finalize ----------------
template<int K,int C1>
__global__ void out_kernel(const float* __restrict__ g1v, const float* __restrict__ b1v,
                           float* __restrict__ out, int chOff)
{
    int i = blockIdx.x*blockDim.x + threadIdx.x;
    if (i >= C1*GRPS) return;
    int c = i / GRPS; int g = i - c*GRPS;
    int b = g >> 10, m = g & 1023;
    float cnt  = (float)(GRPS*K);
    float mean = g_stats[256+c]/cnt;
    float var  = g_stats[384+c]/cnt - mean*mean;
    float a    = g1v[c]/sqrtf(var + 1e-5f);
    float bb   = b1v[c] - mean*a;
    float v1   = a*g_rawmax[c*GRPS + g] + bb;
    float v2   = a*g_rawmin[c*GRPS + g] + bb;
    out[XYZ_OUT + ((size_t)b*320 + chOff + c)*MM + m] = fmaxf(gelu_exact(v1), gelu_exact(v2));
}

// ---------------- launch ----------------
extern "C" void kernel_launch(void* const* d_in, const int* in_sizes, int n_in,
                              void* d_out, int out_size)
{
    const float* xyz  = (const float*)d_in[0];
    const float* feat = (const float*)d_in[1];
    const float* w00  = (const float*)d_in[2];
    const float* w01  = (const float*)d_in[3];
    const float* w10  = (const float*)d_in[4];
    const float* w11  = (const float*)d_in[5];
    const float* w20  = (const float*)d_in[6];
    const float* w21  = (const float*)d_in[7];
    const float* g00  = (const float*)d_in[8];
    const float* b00  = (const float*)d_in[9];
    const float* g01  = (const float*)d_in[10];
    const float* b01  = (const float*)d_in[11];
    const float* g10  = (const float*)d_in[12];
    const float* b10  = (const float*)d_in[13];
    const float* g11  = (const float*)d_in[14];
    const float* b11  = (const float*)d_in[15];
    const float* g20  = (const float*)d_in[16];
    const float* b20  = (const float*)d_in[17];
    const float* g21  = (const float*)d_in[18];
    const float* b21  = (const float*)d_in[19];
    float* out = (float*)d_out;
    float* newxyz = out;

    const int smFPS = 3*NN*4;
    const int smBQ  = 3*NN*4;
    const int smA32 = (9*128*4 + 2*9*2*32)*16 + 2*32*4;
    const int smA64 = (9*128*4 + 2*9*4*32)*16 + 2*64*4;
    const int smC0  = (4*128*4 + 2*4*4*32)*16 + (2*32 + 2*64)*4;
    const int smC12 = (8*256*4 + 2*8*8*32)*16 + (2*64 + 2*128)*4;

    cudaFuncSetAttribute(fps_kernel,          cudaFuncAttributeMaxDynamicSharedMemorySize, smFPS);
    cudaFuncSetAttribute(ballq_kernel,        cudaFuncAttributeMaxDynamicSharedMemorySize, smBQ);
    cudaFuncSetAttribute(passA_kernel<16,32>, cudaFuncAttributeMaxDynamicSharedMemorySize, smA32);
    cudaFuncSetAttribute(passA_kernel<32,64>, cudaFuncAttributeMaxDynamicSharedMemorySize, smA64);
    cudaFuncSetAttribute(passA_kernel<64,64>, cudaFuncAttributeMaxDynamicSharedMemorySize, smA64);
    cudaFuncSetAttribute(passC_kernel<16,32,64,128,256>,  cudaFuncAttributeMaxDynamicSharedMemorySize, smC0);
    cudaFuncSetAttribute(passC_kernel<32,64,128,256,512>, cudaFuncAttributeMaxDynamicSharedMemorySize, smC12);
    cudaFuncSetAttribute(passC_kernel<64,64,128,256,512>, cudaFuncAttributeMaxDynamicSharedMemorySize, smC12);

    fps_kernel<<<BB, 1024, smFPS>>>(xyz, newxyz);
    ballq_kernel<<<GRPS/8, 256, smBQ>>>(xyz, newxyz);

    // scale 0: k=16, C0=32, C1=64
    zero_stats_kernel<<<1,512>>>();
    passA_kernel<16,32><<<GRPS*16/128, 256, smA32>>>(xyz, feat, newxyz, 0, w00);
    passC_kernel<16,32,64,128,256><<<GRPS*16/128, 256, smC0>>>(w01, g00, b00);
    out_kernel<16,64><<<(64*GRPS)/256, 256>>>(g01, b01, out, 0);

    // scale 1: k=32, C0=64, C1=128
    zero_stats_kernel<<<1,512>>>();
    passA_kernel<32,64><<<GRPS*32/128, 256, smA64>>>(xyz, feat, newxyz, 16*GRPS, w10);
    passC_kernel<32,64,128,256,512><<<GRPS*32/256, 512, smC12>>>(w11, g10, b10);
    out_kernel<32,128><<<(128*GRPS)/256, 256>>>(g11, b11, out, 64);

    // scale 2: k=64, C0=64, C1=128
    zero_stats_kernel<<<1,512>>>();
    passA_kernel<64,64><<<GRPS*64/128, 256, smA64>>>(xyz, feat, newxyz, 48*GRPS, w20);
    passC_kernel<64,64,128,256,512><<<GRPS*64/256, 512, smC12>>>(w21, g20, b20);
    out_kernel<64,128><<<(128*GRPS)/256, 256>>>(g21, b21, out, 192);
}